// round 2
// baseline (speedup 1.0000x reference)
#include <cuda_runtime.h>

#define L 128
#define BATCH 64

__device__ __forceinline__ float2 cmulf(float2 a, float2 b) {
    return make_float2(a.x*b.x - a.y*b.y, a.x*b.y + a.y*b.x);
}
__device__ __forceinline__ float2 conjf2(float2 a) { return make_float2(a.x, -a.y); }

// 8 MB scratch for the Wilson-seed (conjugated path), (B, L, L) complex
__device__ float2 g_seed[BATCH * L * L];

// ---------------------------------------------------------------------------
// Kernel 1: Wilson seed. One block per batch element.
//   x_axis[i] = prod_{k<i} ux[b,k,0]     (exclusive prefix, warp scan, warp 0)
//   path[i,j] = x_axis[i] * prod_{m<j} uy[b,i,m]   (one warp per row)
//   seed = conj(path)
// ---------------------------------------------------------------------------
__global__ __launch_bounds__(256) void seed_kernel(const float* __restrict__ x) {
    int b    = blockIdx.x;
    int tid  = threadIdx.x;
    int w    = tid >> 5;
    int lane = tid & 31;
    __shared__ float2 s_ax[L];
    const float* X = x + (size_t)b * 4 * L * L;

    if (w == 0) {
        // exclusive prefix product of ux[:,k,0] over k (column 0, stride L)
        float2 u[4];
        #pragma unroll
        for (int t = 0; t < 4; t++) {
            int k = lane * 4 + t;
            u[t] = make_float2(X[0 * L * L + k * L], X[1 * L * L + k * L]);
        }
        float2 e1 = u[0];
        float2 e2 = cmulf(e1, u[1]);
        float2 e3 = cmulf(e2, u[2]);
        float2 v  = cmulf(e3, u[3]);   // lane total
        #pragma unroll
        for (int off = 1; off < 32; off <<= 1) {
            float vx = __shfl_up_sync(0xffffffffu, v.x, off);
            float vy = __shfl_up_sync(0xffffffffu, v.y, off);
            if (lane >= off) v = cmulf(make_float2(vx, vy), v);
        }
        float wx = __shfl_up_sync(0xffffffffu, v.x, 1);
        float wy = __shfl_up_sync(0xffffffffu, v.y, 1);
        float2 W = (lane == 0) ? make_float2(1.f, 0.f) : make_float2(wx, wy);
        s_ax[lane * 4 + 0] = W;
        s_ax[lane * 4 + 1] = cmulf(W, e1);
        s_ax[lane * 4 + 2] = cmulf(W, e2);
        s_ax[lane * 4 + 3] = cmulf(W, e3);
    }
    __syncthreads();

    float2* seed = g_seed + b * L * L;
    for (int i = w; i < L; i += 8) {
        const float4* pr = reinterpret_cast<const float4*>(X + 2 * L * L + i * L);
        const float4* pi = reinterpret_cast<const float4*>(X + 3 * L * L + i * L);
        float4 r4 = pr[lane], i4 = pi[lane];
        float2 u0 = make_float2(r4.x, i4.x);
        float2 u1 = make_float2(r4.y, i4.y);
        float2 u2 = make_float2(r4.z, i4.z);
        float2 u3 = make_float2(r4.w, i4.w);
        float2 e1 = u0;
        float2 e2 = cmulf(e1, u1);
        float2 e3 = cmulf(e2, u2);
        float2 v  = cmulf(e3, u3);
        #pragma unroll
        for (int off = 1; off < 32; off <<= 1) {
            float vx = __shfl_up_sync(0xffffffffu, v.x, off);
            float vy = __shfl_up_sync(0xffffffffu, v.y, off);
            if (lane >= off) v = cmulf(make_float2(vx, vy), v);
        }
        float wx = __shfl_up_sync(0xffffffffu, v.x, 1);
        float wy = __shfl_up_sync(0xffffffffu, v.y, 1);
        float2 W = (lane == 0) ? make_float2(1.f, 0.f) : make_float2(wx, wy);
        float2 base = cmulf(s_ax[i], W);
        float2 p0 = base;
        float2 p1 = cmulf(base, e1);
        float2 p2 = cmulf(base, e2);
        float2 p3 = cmulf(base, e3);
        float4* dst = reinterpret_cast<float4*>(seed + i * L + lane * 4);
        dst[0] = make_float4(p0.x, -p0.y, p1.x, -p1.y);   // store conj
        dst[1] = make_float4(p2.x, -p2.y, p3.x, -p3.y);
    }
}

// ---------------------------------------------------------------------------
// Kernel 2: fully-fused features -> lconv1 -> modReLU -> lconv2 -> modReLU ->
// readout, on 16x16 output tiles with periodic halo.
// ---------------------------------------------------------------------------
struct Smem {
    float2 lx[24][25];       // ux complex, region [-4, 20)
    float2 ly[24][25];       // uy complex
    float2 f0[3][20][21];    // initial features, region [-2, 18)
    float2 g1[16][18][19];   // layer-1 activations, region [-1, 17)
    float  pc[22][23];       // cos(plaquette), region [-3, 19)
    float  w1[15][16];       // [term*3+i][o]: center, fwd0, fwd1, bwd0, bwd1
    float  w2[80][8];        // [term*16+i][o]
    float  b1[16];
    float  b2[8];
    float  ro[8];
    float  rob;
};

__global__ __launch_bounds__(256) void main_kernel(
    const float* __restrict__ x,
    const float* __restrict__ c1, const float* __restrict__ fw1,
    const float* __restrict__ bw1, const float* __restrict__ b1g,
    const float* __restrict__ c2, const float* __restrict__ fw2,
    const float* __restrict__ bw2, const float* __restrict__ b2g,
    const float* __restrict__ row, const float* __restrict__ rob,
    float* __restrict__ out)
{
    extern __shared__ unsigned char smem_raw[];
    Smem& S = *reinterpret_cast<Smem*>(smem_raw);
    int tid = threadIdx.x;
    int b   = blockIdx.z;
    int ti  = blockIdx.y * 16;
    int tj  = blockIdx.x * 16;
    const float* X = x + (size_t)b * 4 * L * L;

    // ---- stage weights into SMEM ----
    for (int t = tid; t < 48; t += 256) S.w1[t % 3][t / 3] = c1[t];
    for (int t = tid; t < 96; t += 256) {
        int mu = t / 48, r = t % 48;
        S.w1[3 + mu * 3 + (r % 3)][r / 3] = fw1[t];
    }
    for (int t = tid; t < 96; t += 256) {
        int mu = t / 48, r = t % 48;
        S.w1[9 + mu * 3 + (r % 3)][r / 3] = bw1[t];
    }
    if (tid < 16) S.b1[tid] = b1g[tid];
    for (int t = tid; t < 128; t += 256) S.w2[t % 16][t / 16] = c2[t];
    {
        int t = tid;  // 256 elements, exactly one per thread
        int mu = t / 128, r = t % 128;
        S.w2[16 + mu * 16 + (r % 16)][r / 16] = fw2[t];
        S.w2[48 + mu * 16 + (r % 16)][r / 16] = bw2[t];
    }
    if (tid < 8) { S.b2[tid] = b2g[tid]; S.ro[tid] = row[tid]; }
    if (tid == 0) S.rob = rob[0];

    // ---- stage A: load link halo (region [-4, 20)) ----
    for (int t = tid; t < 24 * 24; t += 256) {
        int r = t / 24, c = t % 24;
        int gi = (ti + r - 4) & 127, gj = (tj + c - 4) & 127;
        int base = gi * L + gj;
        S.lx[r][c] = make_float2(X[base],           X[L * L + base]);
        S.ly[r][c] = make_float2(X[2 * L * L + base], X[3 * L * L + base]);
    }
    __syncthreads();

    // ---- stage B: cos(plaquette) via complex product (region [-3, 19)) ----
    for (int t = tid; t < 22 * 22; t += 256) {
        int r = t / 22, c = t % 22;   // x-local = (r+1, c+1)
        float2 p = cmulf(S.lx[r + 1][c + 1], S.ly[r + 2][c + 1]);
        p = cmulf(p, conjf2(S.lx[r + 1][c + 2]));
        p = cmulf(p, conjf2(S.ly[r + 1][c + 1]));
        float n = p.x * p.x + p.y * p.y;
        S.pc[r][c] = p.x * rsqrtf(fmaxf(n, 1e-38f));
    }
    __syncthreads();

    // ---- stage C: initial features (region [-2, 18)) ----
    const float2* seed = g_seed + b * L * L;
    for (int t = tid; t < 20 * 20; t += 256) {
        int r = t / 20, c = t % 20;   // pc-local = (r+1, c+1)
        int gi = (ti + r - 2) & 127, gj = (tj + c - 2) & 127;
        float2 sd = seed[gi * L + gj];
        float pcc  = S.pc[r + 1][c + 1];
        float pavg = 0.2f * (pcc + S.pc[r][c + 1] + S.pc[r + 2][c + 1]
                                 + S.pc[r + 1][c] + S.pc[r + 1][c + 2]);
        S.f0[0][r][c] = sd;
        S.f0[1][r][c] = make_float2(sd.x * pcc,  sd.y * pcc);
        S.f0[2][r][c] = make_float2(sd.x * pavg, sd.y * pavg);
    }
    __syncthreads();

    // ---- stage D: lconv1 + modReLU (region [-1, 17)) ----
    for (int t = tid; t < 18 * 18; t += 256) {
        int r = t / 18, c = t % 18;   // f0-local = (r+1, c+1); x-local = (r+3, c+3)
        float2 v[15];
        #pragma unroll
        for (int i = 0; i < 3; i++) v[i] = S.f0[i][r + 1][c + 1];
        float2 l0 = S.lx[r + 3][c + 3], l1 = S.ly[r + 3][c + 3];
        float2 m0 = conjf2(S.lx[r + 2][c + 3]), m1 = conjf2(S.ly[r + 3][c + 2]);
        #pragma unroll
        for (int i = 0; i < 3; i++) {
            v[3  + i] = cmulf(l0, S.f0[i][r + 2][c + 1]);
            v[6  + i] = cmulf(l1, S.f0[i][r + 1][c + 2]);
            v[9  + i] = cmulf(m0, S.f0[i][r    ][c + 1]);
            v[12 + i] = cmulf(m1, S.f0[i][r + 1][c    ]);
        }
        float ar[16], ai[16];
        #pragma unroll
        for (int o = 0; o < 16; o++) { ar[o] = 0.f; ai[o] = 0.f; }
        #pragma unroll
        for (int k = 0; k < 15; k++) {
            float2 vk = v[k];
            #pragma unroll
            for (int o = 0; o < 16; o++) {
                float wv = S.w1[k][o];
                ar[o] = fmaf(wv, vk.x, ar[o]);
                ai[o] = fmaf(wv, vk.y, ai[o]);
            }
        }
        #pragma unroll
        for (int o = 0; o < 16; o++) {
            float mag = sqrtf(fmaf(ar[o], ar[o], fmaf(ai[o], ai[o], 1e-12f)));
            float act = fmaxf(mag + S.b1[o], 0.f);
            float sc  = act / fmaxf(mag, 1e-12f);
            S.g1[o][r][c] = make_float2(ar[o] * sc, ai[o] * sc);
        }
    }
    __syncthreads();

    // ---- stage E: lconv2 + modReLU + readout (16x16 outputs) ----
    {
        int r = tid >> 4, c = tid & 15;   // g1-local = (r+1, c+1); x-local = (r+4, c+4)
        float ar[8], ai[8];
        #pragma unroll
        for (int o = 0; o < 8; o++) { ar[o] = 0.f; ai[o] = 0.f; }
        float2 l0 = S.lx[r + 4][c + 4], l1 = S.ly[r + 4][c + 4];
        float2 m0 = conjf2(S.lx[r + 3][c + 4]), m1 = conjf2(S.ly[r + 4][c + 3]);

        #pragma unroll 4
        for (int i = 0; i < 16; i++) {               // center
            float2 vv = S.g1[i][r + 1][c + 1];
            #pragma unroll
            for (int o = 0; o < 8; o++) {
                float wv = S.w2[i][o];
                ar[o] = fmaf(wv, vv.x, ar[o]); ai[o] = fmaf(wv, vv.y, ai[o]);
            }
        }
        #pragma unroll 4
        for (int i = 0; i < 16; i++) {               // fwd mu=0
            float2 vv = cmulf(l0, S.g1[i][r + 2][c + 1]);
            #pragma unroll
            for (int o = 0; o < 8; o++) {
                float wv = S.w2[16 + i][o];
                ar[o] = fmaf(wv, vv.x, ar[o]); ai[o] = fmaf(wv, vv.y, ai[o]);
            }
        }
        #pragma unroll 4
        for (int i = 0; i < 16; i++) {               // fwd mu=1
            float2 vv = cmulf(l1, S.g1[i][r + 1][c + 2]);
            #pragma unroll
            for (int o = 0; o < 8; o++) {
                float wv = S.w2[32 + i][o];
                ar[o] = fmaf(wv, vv.x, ar[o]); ai[o] = fmaf(wv, vv.y, ai[o]);
            }
        }
        #pragma unroll 4
        for (int i = 0; i < 16; i++) {               // bwd mu=0
            float2 vv = cmulf(m0, S.g1[i][r][c + 1]);
            #pragma unroll
            for (int o = 0; o < 8; o++) {
                float wv = S.w2[48 + i][o];
                ar[o] = fmaf(wv, vv.x, ar[o]); ai[o] = fmaf(wv, vv.y, ai[o]);
            }
        }
        #pragma unroll 4
        for (int i = 0; i < 16; i++) {               // bwd mu=1
            float2 vv = cmulf(m1, S.g1[i][r + 1][c]);
            #pragma unroll
            for (int o = 0; o < 8; o++) {
                float wv = S.w2[64 + i][o];
                ar[o] = fmaf(wv, vv.x, ar[o]); ai[o] = fmaf(wv, vv.y, ai[o]);
            }
        }

        float o_val = S.rob;
        #pragma unroll
        for (int o = 0; o < 8; o++) {
            float mag = sqrtf(fmaf(ar[o], ar[o], fmaf(ai[o], ai[o], 1e-12f)));
            float act = fmaxf(mag + S.b2[o], 0.f);
            float sc  = act / fmaxf(mag, 1e-12f);
            float fr = ar[o] * sc, fi = ai[o] * sc;
            o_val = fmaf(S.ro[o], fmaf(fr, fr, fi * fi), o_val);
        }
        out[(size_t)b * L * L + (ti + r) * L + (tj + c)] = o_val;
    }
}

extern "C" void kernel_launch(void* const* d_in, const int* in_sizes, int n_in,
                              void* d_out, int out_size) {
    const float* x   = (const float*)d_in[0];
    const float* c1  = (const float*)d_in[1];
    const float* fw1 = (const float*)d_in[2];
    const float* bw1 = (const float*)d_in[3];
    const float* b1  = (const float*)d_in[4];
    const float* c2  = (const float*)d_in[5];
    const float* fw2 = (const float*)d_in[6];
    const float* bw2 = (const float*)d_in[7];
    const float* b2  = (const float*)d_in[8];
    const float* row = (const float*)d_in[9];
    const float* rob = (const float*)d_in[10];
    float* out = (float*)d_out;
    (void)in_sizes; (void)n_in; (void)out_size;

    seed_kernel<<<64, 256>>>(x);

    cudaFuncSetAttribute(main_kernel, cudaFuncAttributeMaxDynamicSharedMemorySize,
                         (int)sizeof(Smem));
    dim3 grid(8, 8, BATCH);
    main_kernel<<<grid, 256, sizeof(Smem)>>>(x, c1, fw1, bw1, b1,
                                             c2, fw2, bw2, b2, row, rob, out);
}

// round 4
// speedup vs baseline: 1.2966x; 1.2966x over previous
#include <cuda_runtime.h>

#define L 128
#define BATCH 64

typedef unsigned long long u64;

__device__ __forceinline__ float2 cmulf(float2 a, float2 b) {
    return make_float2(a.x*b.x - a.y*b.y, a.x*b.y + a.y*b.x);
}
__device__ __forceinline__ float2 conjf2(float2 a) { return make_float2(a.x, -a.y); }

__device__ __forceinline__ u64 pk2(float a, float b) {
    u64 r; asm("mov.b64 %0, {%1,%2};" : "=l"(r) : "f"(a), "f"(b)); return r;
}
__device__ __forceinline__ void unpk2(u64 v, float& a, float& b) {
    asm("mov.b64 {%0,%1}, %2;" : "=f"(a), "=f"(b) : "l"(v));
}
__device__ __forceinline__ u64 ffma2(u64 a, u64 b, u64 c) {
    u64 d; asm("fma.rn.f32x2 %0, %1, %2, %3;" : "=l"(d) : "l"(a), "l"(b), "l"(c)); return d;
}
__device__ __forceinline__ u64 fmul2(u64 a, u64 b) {
    u64 d; asm("mul.rn.f32x2 %0, %1, %2;" : "=l"(d) : "l"(a), "l"(b)); return d;
}

// ---------------- constant weight banks ----------------
__constant__ float2 CWD[15][8];      // layer1 packed: [tap*3+i][o-pair], (w[2p][i], w[2p+1][i])
__constant__ float2 CC2[8][8];       // center2 [o][i-pair]  (raw reinterpret of [8][16])
__constant__ float2 CFW2[2][8][8];   // fwd_w2
__constant__ float2 CBW2[2][8][8];   // bwd_w2
__constant__ float  CB1[16];
__constant__ float  CB2[8];
__constant__ float  CRO[8];
__constant__ float  CROB[1];

// staging buffer for layer-1 packed weights (written by prep kernel)
__device__ float2 g_cwD[15][8];

// 8 MB scratch for the Wilson-seed (conjugated path), (B, L, L) complex
__device__ float2 g_seed[BATCH * L * L];

// ---------------------------------------------------------------------------
// prep: pack layer-1 weights into o-pair layout
// ---------------------------------------------------------------------------
__global__ void prep_kernel(const float* __restrict__ c1, const float* __restrict__ fw1,
                            const float* __restrict__ bw1) {
    int t = threadIdx.x;
    if (t < 120) {
        int k = t / 8, p = t % 8;
        int tap = k / 3, i = k % 3;
        const float* W;
        if      (tap == 0) W = c1;
        else if (tap == 1) W = fw1;
        else if (tap == 2) W = fw1 + 48;
        else if (tap == 3) W = bw1;
        else               W = bw1 + 48;
        g_cwD[k][p] = make_float2(W[(2*p)*3 + i], W[(2*p+1)*3 + i]);
    }
}

// ---------------------------------------------------------------------------
// Kernel 1: Wilson seed (unchanged from R2 — ~2 us)
// ---------------------------------------------------------------------------
__global__ __launch_bounds__(256) void seed_kernel(const float* __restrict__ x) {
    int b    = blockIdx.x;
    int tid  = threadIdx.x;
    int w    = tid >> 5;
    int lane = tid & 31;
    __shared__ float2 s_ax[L];
    const float* X = x + (size_t)b * 4 * L * L;

    if (w == 0) {
        float2 u[4];
        #pragma unroll
        for (int t = 0; t < 4; t++) {
            int k = lane * 4 + t;
            u[t] = make_float2(X[0 * L * L + k * L], X[1 * L * L + k * L]);
        }
        float2 e1 = u[0];
        float2 e2 = cmulf(e1, u[1]);
        float2 e3 = cmulf(e2, u[2]);
        float2 v  = cmulf(e3, u[3]);
        #pragma unroll
        for (int off = 1; off < 32; off <<= 1) {
            float vx = __shfl_up_sync(0xffffffffu, v.x, off);
            float vy = __shfl_up_sync(0xffffffffu, v.y, off);
            if (lane >= off) v = cmulf(make_float2(vx, vy), v);
        }
        float wx = __shfl_up_sync(0xffffffffu, v.x, 1);
        float wy = __shfl_up_sync(0xffffffffu, v.y, 1);
        float2 W = (lane == 0) ? make_float2(1.f, 0.f) : make_float2(wx, wy);
        s_ax[lane * 4 + 0] = W;
        s_ax[lane * 4 + 1] = cmulf(W, e1);
        s_ax[lane * 4 + 2] = cmulf(W, e2);
        s_ax[lane * 4 + 3] = cmulf(W, e3);
    }
    __syncthreads();

    float2* seed = g_seed + b * L * L;
    for (int i = w; i < L; i += 8) {
        const float4* pr = reinterpret_cast<const float4*>(X + 2 * L * L + i * L);
        const float4* pi = reinterpret_cast<const float4*>(X + 3 * L * L + i * L);
        float4 r4 = pr[lane], i4 = pi[lane];
        float2 u0 = make_float2(r4.x, i4.x);
        float2 u1 = make_float2(r4.y, i4.y);
        float2 u2 = make_float2(r4.z, i4.z);
        float2 u3 = make_float2(r4.w, i4.w);
        float2 e1 = u0;
        float2 e2 = cmulf(e1, u1);
        float2 e3 = cmulf(e2, u2);
        float2 v  = cmulf(e3, u3);
        #pragma unroll
        for (int off = 1; off < 32; off <<= 1) {
            float vx = __shfl_up_sync(0xffffffffu, v.x, off);
            float vy = __shfl_up_sync(0xffffffffu, v.y, off);
            if (lane >= off) v = cmulf(make_float2(vx, vy), v);
        }
        float wx = __shfl_up_sync(0xffffffffu, v.x, 1);
        float wy = __shfl_up_sync(0xffffffffu, v.y, 1);
        float2 W = (lane == 0) ? make_float2(1.f, 0.f) : make_float2(wx, wy);
        float2 base = cmulf(s_ax[i], W);
        float2 p0 = base;
        float2 p1 = cmulf(base, e1);
        float2 p2 = cmulf(base, e2);
        float2 p3 = cmulf(base, e3);
        float4* dst = reinterpret_cast<float4*>(seed + i * L + lane * 4);
        dst[0] = make_float4(p0.x, -p0.y, p1.x, -p1.y);
        dst[1] = make_float4(p2.x, -p2.y, p3.x, -p3.y);
    }
}

// ---------------------------------------------------------------------------
// Kernel 2: fused main kernel
// ---------------------------------------------------------------------------
struct Smem {
    float2 lx[24][25];        // ux, region [-4, 20)
    float2 ly[24][25];        // uy
    float  pc[22][23];        // cos(plaquette), region [-3, 19)
    float  f0r[3][20][21];    // initial features SoA, region [-2, 18)
    float  f0i[3][20][21];
    float  g1r[18][19][18];   // layer-1 activations SoA [row][col][ch(16)+pad2], region [-1,17)
    float  g1i[18][19][18];
};

// layer-2 tap: accumulate  link * (W @ g(neighbor))  into packed partial sums
__device__ __forceinline__ void tapE(const float* __restrict__ gr,
                                     const float* __restrict__ gi,
                                     const float2 (&W)[8][8],
                                     float tx, float ty,
                                     u64* ACCr, u64* ACCi) {
    u64 TAr[8], TAi[8];
    #pragma unroll
    for (int o = 0; o < 8; o++) { TAr[o] = 0ull; TAi[o] = 0ull; }
    #pragma unroll
    for (int ip = 0; ip < 8; ip++) {
        u64 vr = *reinterpret_cast<const u64*>(gr + 2 * ip);
        u64 vi = *reinterpret_cast<const u64*>(gi + 2 * ip);
        #pragma unroll
        for (int o = 0; o < 8; o++) {
            u64 w = *reinterpret_cast<const u64*>(&W[o][ip]);
            TAr[o] = ffma2(w, vr, TAr[o]);
            TAi[o] = ffma2(w, vi, TAi[o]);
        }
    }
    u64 txx = pk2(tx, tx), tyy = pk2(ty, ty), nty = pk2(-ty, -ty);
    #pragma unroll
    for (int o = 0; o < 8; o++) {
        ACCr[o] = ffma2(txx, TAr[o], ffma2(nty, TAi[o], ACCr[o]));
        ACCi[o] = ffma2(txx, TAi[o], ffma2(tyy, TAr[o], ACCi[o]));
    }
}

__global__ __launch_bounds__(256, 2) void main_kernel(
    const float* __restrict__ x, float* __restrict__ out)
{
    extern __shared__ unsigned char smem_raw[];
    Smem& S = *reinterpret_cast<Smem*>(smem_raw);
    int tid = threadIdx.x;
    int b   = blockIdx.z;
    int ti  = blockIdx.y * 16;
    int tj  = blockIdx.x * 16;
    const float* X = x + (size_t)b * 4 * L * L;

    // ---- stage A: link halo (region [-4, 20)) ----
    for (int t = tid; t < 24 * 24; t += 256) {
        int r = t / 24, c = t % 24;
        int gi = (ti + r - 4) & 127, gj = (tj + c - 4) & 127;
        int base = gi * L + gj;
        S.lx[r][c] = make_float2(X[base],             X[L * L + base]);
        S.ly[r][c] = make_float2(X[2 * L * L + base], X[3 * L * L + base]);
    }
    __syncthreads();

    // ---- stage B: cos(plaquette) (region [-3, 19)) ----
    for (int t = tid; t < 22 * 22; t += 256) {
        int r = t / 22, c = t % 22;
        float2 p = cmulf(S.lx[r + 1][c + 1], S.ly[r + 2][c + 1]);
        p = cmulf(p, conjf2(S.lx[r + 1][c + 2]));
        p = cmulf(p, conjf2(S.ly[r + 1][c + 1]));
        float n = p.x * p.x + p.y * p.y;
        S.pc[r][c] = p.x * rsqrtf(fmaxf(n, 1e-38f));
    }
    __syncthreads();

    // ---- stage C: initial features (region [-2, 18)) ----
    const float2* seed = g_seed + b * L * L;
    for (int t = tid; t < 20 * 20; t += 256) {
        int r = t / 20, c = t % 20;
        int gi = (ti + r - 2) & 127, gj = (tj + c - 2) & 127;
        float2 sd = seed[gi * L + gj];
        float pcc  = S.pc[r + 1][c + 1];
        float pavg = 0.2f * (pcc + S.pc[r][c + 1] + S.pc[r + 2][c + 1]
                                 + S.pc[r + 1][c] + S.pc[r + 1][c + 2]);
        S.f0r[0][r][c] = sd.x;        S.f0i[0][r][c] = sd.y;
        S.f0r[1][r][c] = sd.x * pcc;  S.f0i[1][r][c] = sd.y * pcc;
        S.f0r[2][r][c] = sd.x * pavg; S.f0i[2][r][c] = sd.y * pavg;
    }
    __syncthreads();

    // ---- stage D: lconv1 + modReLU (region [-1, 17)) ----
    for (int t = tid; t < 18 * 18; t += 256) {
        int r = t / 18, c = t % 18;    // f0 idx = (r+1, c+1); x-local = (r+3, c+3)
        float vr[15], vi[15];
        #pragma unroll
        for (int i = 0; i < 3; i++) {
            vr[i] = S.f0r[i][r + 1][c + 1];
            vi[i] = S.f0i[i][r + 1][c + 1];
        }
        float2 l0 = S.lx[r + 3][c + 3], l1 = S.ly[r + 3][c + 3];
        float2 m0 = S.lx[r + 2][c + 3], m1 = S.ly[r + 3][c + 2];  // conj applied inline
        #pragma unroll
        for (int i = 0; i < 3; i++) {
            float fr, fi2;
            fr = S.f0r[i][r + 2][c + 1]; fi2 = S.f0i[i][r + 2][c + 1];
            vr[3 + i]  = l0.x * fr - l0.y * fi2;  vi[3 + i]  = l0.x * fi2 + l0.y * fr;
            fr = S.f0r[i][r + 1][c + 2]; fi2 = S.f0i[i][r + 1][c + 2];
            vr[6 + i]  = l1.x * fr - l1.y * fi2;  vi[6 + i]  = l1.x * fi2 + l1.y * fr;
            fr = S.f0r[i][r    ][c + 1]; fi2 = S.f0i[i][r    ][c + 1];
            vr[9 + i]  = m0.x * fr + m0.y * fi2;  vi[9 + i]  = m0.x * fi2 - m0.y * fr;
            fr = S.f0r[i][r + 1][c    ]; fi2 = S.f0i[i][r + 1][c    ];
            vr[12 + i] = m1.x * fr + m1.y * fi2;  vi[12 + i] = m1.x * fi2 - m1.y * fr;
        }
        u64 AR[8], AI[8];
        #pragma unroll
        for (int p = 0; p < 8; p++) { AR[p] = 0ull; AI[p] = 0ull; }
        #pragma unroll
        for (int k = 0; k < 15; k++) {
            u64 rr = pk2(vr[k], vr[k]);
            u64 ii = pk2(vi[k], vi[k]);
            #pragma unroll
            for (int p = 0; p < 8; p++) {
                u64 w = *reinterpret_cast<const u64*>(&CWD[k][p]);
                AR[p] = ffma2(w, rr, AR[p]);
                AI[p] = ffma2(w, ii, AI[p]);
            }
        }
        #pragma unroll
        for (int p = 0; p < 8; p++) {
            float a0r, a1r, a0i, a1i;
            unpk2(AR[p], a0r, a1r);
            unpk2(AI[p], a0i, a1i);
            float m2a = fmaf(a0r, a0r, fmaf(a0i, a0i, 1e-12f));
            float m2b = fmaf(a1r, a1r, fmaf(a1i, a1i, 1e-12f));
            float q0 = rsqrtf(m2a), q1 = rsqrtf(m2b);
            float s0 = fmaxf(fmaf(CB1[2 * p], q0, 1.f), 0.f);
            float s1 = fmaxf(fmaf(CB1[2 * p + 1], q1, 1.f), 0.f);
            u64 S2 = pk2(s0, s1);
            *reinterpret_cast<u64*>(&S.g1r[r][c][2 * p]) = fmul2(AR[p], S2);
            *reinterpret_cast<u64*>(&S.g1i[r][c][2 * p]) = fmul2(AI[p], S2);
        }
    }
    __syncthreads();

    // ---- stage E: lconv2 + modReLU + readout (16x16 outputs) ----
    {
        int r = tid >> 4, c = tid & 15;   // g1 idx = (r+1, c+1); x-local = (r+4, c+4)
        u64 ACCr[8], ACCi[8];
        #pragma unroll
        for (int o = 0; o < 8; o++) { ACCr[o] = 0ull; ACCi[o] = 0ull; }

        // center tap: accumulate directly (no link)
        {
            const float* gr = &S.g1r[r + 1][c + 1][0];
            const float* gi = &S.g1i[r + 1][c + 1][0];
            #pragma unroll
            for (int ip = 0; ip < 8; ip++) {
                u64 vrp = *reinterpret_cast<const u64*>(gr + 2 * ip);
                u64 vip = *reinterpret_cast<const u64*>(gi + 2 * ip);
                #pragma unroll
                for (int o = 0; o < 8; o++) {
                    u64 w = *reinterpret_cast<const u64*>(&CC2[o][ip]);
                    ACCr[o] = ffma2(w, vrp, ACCr[o]);
                    ACCi[o] = ffma2(w, vip, ACCi[o]);
                }
            }
        }
        float2 l0 = S.lx[r + 4][c + 4], l1 = S.ly[r + 4][c + 4];
        float2 m0 = S.lx[r + 3][c + 4], m1 = S.ly[r + 4][c + 3];
        tapE(&S.g1r[r + 2][c + 1][0], &S.g1i[r + 2][c + 1][0], CFW2[0],  l0.x,  l0.y, ACCr, ACCi);
        tapE(&S.g1r[r + 1][c + 2][0], &S.g1i[r + 1][c + 2][0], CFW2[1],  l1.x,  l1.y, ACCr, ACCi);
        tapE(&S.g1r[r    ][c + 1][0], &S.g1i[r    ][c + 1][0], CBW2[0],  m0.x, -m0.y, ACCr, ACCi);
        tapE(&S.g1r[r + 1][c    ][0], &S.g1i[r + 1][c    ][0], CBW2[1],  m1.x, -m1.y, ACCr, ACCi);

        float val = CROB[0];
        #pragma unroll
        for (int o = 0; o < 8; o++) {
            float rl, rh, il, ih;
            unpk2(ACCr[o], rl, rh);
            unpk2(ACCi[o], il, ih);
            float ar = rl + rh, ai = il + ih;
            float m2 = fmaf(ar, ar, fmaf(ai, ai, 1e-12f));
            float q  = rsqrtf(m2);
            float sc = fmaxf(fmaf(CB2[o], q, 1.f), 0.f);
            val = fmaf(CRO[o], m2 * sc * sc, val);
        }
        out[(size_t)b * L * L + (ti + r) * L + (tj + c)] = val;
    }
}

extern "C" void kernel_launch(void* const* d_in, const int* in_sizes, int n_in,
                              void* d_out, int out_size) {
    const float* x   = (const float*)d_in[0];
    const float* c1  = (const float*)d_in[1];
    const float* fw1 = (const float*)d_in[2];
    const float* bw1 = (const float*)d_in[3];
    const float* b1  = (const float*)d_in[4];
    const float* c2  = (const float*)d_in[5];
    const float* fw2 = (const float*)d_in[6];
    const float* bw2 = (const float*)d_in[7];
    const float* b2  = (const float*)d_in[8];
    const float* row = (const float*)d_in[9];
    const float* rob = (const float*)d_in[10];
    float* out = (float*)d_out;
    (void)in_sizes; (void)n_in; (void)out_size;

    // pack layer-1 weights, then stage all weights into constant memory (D2D, capture-legal)
    prep_kernel<<<1, 128>>>(c1, fw1, bw1);
    void* cwd_ptr = nullptr;
    cudaGetSymbolAddress(&cwd_ptr, g_cwD);
    cudaMemcpyToSymbolAsync(CWD,  cwd_ptr, 15 * 8 * sizeof(float2), 0, cudaMemcpyDeviceToDevice);
    cudaMemcpyToSymbolAsync(CC2,  c2,  8 * 16 * sizeof(float),  0, cudaMemcpyDeviceToDevice);
    cudaMemcpyToSymbolAsync(CFW2, fw2, 2 * 8 * 16 * sizeof(float), 0, cudaMemcpyDeviceToDevice);
    cudaMemcpyToSymbolAsync(CBW2, bw2, 2 * 8 * 16 * sizeof(float), 0, cudaMemcpyDeviceToDevice);
    cudaMemcpyToSymbolAsync(CB1,  b1,  16 * sizeof(float), 0, cudaMemcpyDeviceToDevice);
    cudaMemcpyToSymbolAsync(CB2,  b2,  8 * sizeof(float),  0, cudaMemcpyDeviceToDevice);
    cudaMemcpyToSymbolAsync(CRO,  row, 8 * sizeof(float),  0, cudaMemcpyDeviceToDevice);
    cudaMemcpyToSymbolAsync(CROB, rob, 1 * sizeof(float),  0, cudaMemcpyDeviceToDevice);

    seed_kernel<<<64, 256>>>(x);

    cudaFuncSetAttribute(main_kernel, cudaFuncAttributeMaxDynamicSharedMemorySize,
                         (int)sizeof(Smem));
    dim3 grid(8, 8, BATCH);
    main_kernel<<<grid, 256, sizeof(Smem)>>>(x, out);
}

// round 5
// speedup vs baseline: 1.3923x; 1.0738x over previous
#include <cuda_runtime.h>

#define L 128
#define BATCH 64

typedef unsigned long long u64;

__device__ __forceinline__ float2 cmulf(float2 a, float2 b) {
    return make_float2(a.x*b.x - a.y*b.y, a.x*b.y + a.y*b.x);
}
__device__ __forceinline__ float2 conjf2(float2 a) { return make_float2(a.x, -a.y); }

__device__ __forceinline__ u64 pk2(float a, float b) {
    u64 r; asm("mov.b64 %0, {%1,%2};" : "=l"(r) : "f"(a), "f"(b)); return r;
}
__device__ __forceinline__ void unpk2(u64 v, float& a, float& b) {
    asm("mov.b64 {%0,%1}, %2;" : "=f"(a), "=f"(b) : "l"(v));
}
__device__ __forceinline__ u64 ffma2(u64 a, u64 b, u64 c) {
    u64 d; asm("fma.rn.f32x2 %0, %1, %2, %3;" : "=l"(d) : "l"(a), "l"(b), "l"(c)); return d;
}
__device__ __forceinline__ u64 fmul2(u64 a, u64 b) {
    u64 d; asm("mul.rn.f32x2 %0, %1, %2;" : "=l"(d) : "l"(a), "l"(b)); return d;
}

// ---------------- consolidated weight bank ----------------
struct CW {
    float wD[15][8][2];    // layer1 packed: [tap*3+i][o-pair][2]
    float c2[8][16];       // center2 raw
    float fw2[2][8][16];
    float bw2[2][8][16];
    float b1[16];
    float b2[8];
    float ro[8];
    float rob;
    float pad;
};
__constant__ CW CWc;
__device__ CW g_stage;                 // filled by seed_kernel block 64

// 8 MB scratch for the Wilson-seed (conjugated path), (B, L, L) complex
__device__ float2 g_seed[BATCH * L * L];

// ---------------------------------------------------------------------------
// Kernel 1: Wilson seed (blocks 0..63) + weight packing (block 64)
// ---------------------------------------------------------------------------
__global__ __launch_bounds__(256) void seed_kernel(
    const float* __restrict__ x,
    const float* __restrict__ c1, const float* __restrict__ fw1,
    const float* __restrict__ bw1, const float* __restrict__ b1,
    const float* __restrict__ c2, const float* __restrict__ fw2,
    const float* __restrict__ bw2, const float* __restrict__ b2,
    const float* __restrict__ ro, const float* __restrict__ rob)
{
    int b    = blockIdx.x;
    int tid  = threadIdx.x;

    if (b == 64) {
        // ---- pack all weights into g_stage ----
        if (tid < 120) {
            int k = tid / 8, p = tid % 8;
            int tap = k / 3, i = k % 3;
            const float* W;
            if      (tap == 0) W = c1;
            else if (tap == 1) W = fw1;
            else if (tap == 2) W = fw1 + 48;
            else if (tap == 3) W = bw1;
            else               W = bw1 + 48;
            g_stage.wD[k][p][0] = W[(2*p)*3 + i];
            g_stage.wD[k][p][1] = W[(2*p+1)*3 + i];
        }
        for (int t = tid; t < 128; t += 256) ((float*)g_stage.c2)[t]  = c2[t];
        if (tid < 256) {
            ((float*)g_stage.fw2)[tid] = fw2[tid];
            ((float*)g_stage.bw2)[tid] = bw2[tid];
        }
        if (tid < 16) g_stage.b1[tid] = b1[tid];
        if (tid < 8)  { g_stage.b2[tid] = b2[tid]; g_stage.ro[tid] = ro[tid]; }
        if (tid == 0) g_stage.rob = rob[0];
        return;
    }

    int w    = tid >> 5;
    int lane = tid & 31;
    __shared__ float2 s_ax[L];
    const float* X = x + (size_t)b * 4 * L * L;

    if (w == 0) {
        float2 u[4];
        #pragma unroll
        for (int t = 0; t < 4; t++) {
            int k = lane * 4 + t;
            u[t] = make_float2(X[0 * L * L + k * L], X[1 * L * L + k * L]);
        }
        float2 e1 = u[0];
        float2 e2 = cmulf(e1, u[1]);
        float2 e3 = cmulf(e2, u[2]);
        float2 v  = cmulf(e3, u[3]);
        #pragma unroll
        for (int off = 1; off < 32; off <<= 1) {
            float vx = __shfl_up_sync(0xffffffffu, v.x, off);
            float vy = __shfl_up_sync(0xffffffffu, v.y, off);
            if (lane >= off) v = cmulf(make_float2(vx, vy), v);
        }
        float wx = __shfl_up_sync(0xffffffffu, v.x, 1);
        float wy = __shfl_up_sync(0xffffffffu, v.y, 1);
        float2 W = (lane == 0) ? make_float2(1.f, 0.f) : make_float2(wx, wy);
        s_ax[lane * 4 + 0] = W;
        s_ax[lane * 4 + 1] = cmulf(W, e1);
        s_ax[lane * 4 + 2] = cmulf(W, e2);
        s_ax[lane * 4 + 3] = cmulf(W, e3);
    }
    __syncthreads();

    float2* seed = g_seed + b * L * L;
    for (int i = w; i < L; i += 8) {
        const float4* pr = reinterpret_cast<const float4*>(X + 2 * L * L + i * L);
        const float4* pi = reinterpret_cast<const float4*>(X + 3 * L * L + i * L);
        float4 r4 = pr[lane], i4 = pi[lane];
        float2 u0 = make_float2(r4.x, i4.x);
        float2 u1 = make_float2(r4.y, i4.y);
        float2 u2 = make_float2(r4.z, i4.z);
        float2 u3 = make_float2(r4.w, i4.w);
        float2 e1 = u0;
        float2 e2 = cmulf(e1, u1);
        float2 e3 = cmulf(e2, u2);
        float2 v  = cmulf(e3, u3);
        #pragma unroll
        for (int off = 1; off < 32; off <<= 1) {
            float vx = __shfl_up_sync(0xffffffffu, v.x, off);
            float vy = __shfl_up_sync(0xffffffffu, v.y, off);
            if (lane >= off) v = cmulf(make_float2(vx, vy), v);
        }
        float wx = __shfl_up_sync(0xffffffffu, v.x, 1);
        float wy = __shfl_up_sync(0xffffffffu, v.y, 1);
        float2 W = (lane == 0) ? make_float2(1.f, 0.f) : make_float2(wx, wy);
        float2 base = cmulf(s_ax[i], W);
        float2 p0 = base;
        float2 p1 = cmulf(base, e1);
        float2 p2 = cmulf(base, e2);
        float2 p3 = cmulf(base, e3);
        float4* dst = reinterpret_cast<float4*>(seed + i * L + lane * 4);
        dst[0] = make_float4(p0.x, -p0.y, p1.x, -p1.y);
        dst[1] = make_float4(p2.x, -p2.y, p3.x, -p3.y);
    }
}

// ---------------------------------------------------------------------------
// Kernel 2: fused main kernel
// ---------------------------------------------------------------------------
struct Smem {
    float2 lx[24][25];        // ux, region [-4, 20)
    float2 ly[24][25];        // uy
    float  pc[22][23];        // cos(plaquette), region [-3, 19)
    float  f0r[3][20][21];    // initial features SoA, region [-2, 18)
    float  f0i[3][20][21];
    float  g1r[18][19][18];   // layer-1 activations SoA, region [-1,17)
    float  g1i[18][19][18];
};

// layer-2 tap: accumulate  link * (W @ g(neighbor)); loads chunked (4 ch-pairs)
// to limit live registers.
__device__ __forceinline__ void tapE(const float* __restrict__ gr,
                                     const float* __restrict__ gi,
                                     const float (&W)[8][16],
                                     float tx, float ty,
                                     u64* ACCr, u64* ACCi) {
    u64 TAr[8], TAi[8];
    #pragma unroll
    for (int o = 0; o < 8; o++) { TAr[o] = 0ull; TAi[o] = 0ull; }
    #pragma unroll
    for (int ch = 0; ch < 2; ch++) {
        u64 vr[4], vi[4];
        #pragma unroll
        for (int j = 0; j < 4; j++) {
            vr[j] = *reinterpret_cast<const u64*>(gr + 8 * ch + 2 * j);
            vi[j] = *reinterpret_cast<const u64*>(gi + 8 * ch + 2 * j);
        }
        #pragma unroll
        for (int j = 0; j < 4; j++) {
            #pragma unroll
            for (int o = 0; o < 8; o++) {
                u64 w = *reinterpret_cast<const u64*>(&W[o][8 * ch + 2 * j]);
                TAr[o] = ffma2(w, vr[j], TAr[o]);
                TAi[o] = ffma2(w, vi[j], TAi[o]);
            }
        }
    }
    u64 txx = pk2(tx, tx), tyy = pk2(ty, ty), nty = pk2(-ty, -ty);
    #pragma unroll
    for (int o = 0; o < 8; o++) {
        ACCr[o] = ffma2(txx, TAr[o], ffma2(nty, TAi[o], ACCr[o]));
        ACCi[o] = ffma2(txx, TAi[o], ffma2(tyy, TAr[o], ACCi[o]));
    }
}

__global__ __launch_bounds__(256, 3) void main_kernel(
    const float* __restrict__ x, float* __restrict__ out)
{
    extern __shared__ unsigned char smem_raw[];
    Smem& S = *reinterpret_cast<Smem*>(smem_raw);
    int tid = threadIdx.x;
    int b   = blockIdx.z;
    int ti  = blockIdx.y * 16;
    int tj  = blockIdx.x * 16;
    const float* X = x + (size_t)b * 4 * L * L;

    // ---- stage A: link halo (region [-4, 20)) ----
    for (int t = tid; t < 24 * 24; t += 256) {
        int r = t / 24, c = t % 24;
        int gi = (ti + r - 4) & 127, gj = (tj + c - 4) & 127;
        int base = gi * L + gj;
        S.lx[r][c] = make_float2(X[base],             X[L * L + base]);
        S.ly[r][c] = make_float2(X[2 * L * L + base], X[3 * L * L + base]);
    }
    __syncthreads();

    // ---- stage B: cos(plaquette) (region [-3, 19)) ----
    for (int t = tid; t < 22 * 22; t += 256) {
        int r = t / 22, c = t % 22;
        float2 p = cmulf(S.lx[r + 1][c + 1], S.ly[r + 2][c + 1]);
        p = cmulf(p, conjf2(S.lx[r + 1][c + 2]));
        p = cmulf(p, conjf2(S.ly[r + 1][c + 1]));
        float n = p.x * p.x + p.y * p.y;
        S.pc[r][c] = p.x * rsqrtf(fmaxf(n, 1e-38f));
    }
    __syncthreads();

    // ---- stage C: initial features (region [-2, 18)) ----
    const float2* seed = g_seed + b * L * L;
    for (int t = tid; t < 20 * 20; t += 256) {
        int r = t / 20, c = t % 20;
        int gi = (ti + r - 2) & 127, gj = (tj + c - 2) & 127;
        float2 sd = seed[gi * L + gj];
        float pcc  = S.pc[r + 1][c + 1];
        float pavg = 0.2f * (pcc + S.pc[r][c + 1] + S.pc[r + 2][c + 1]
                                 + S.pc[r + 1][c] + S.pc[r + 1][c + 2]);
        S.f0r[0][r][c] = sd.x;        S.f0i[0][r][c] = sd.y;
        S.f0r[1][r][c] = sd.x * pcc;  S.f0i[1][r][c] = sd.y * pcc;
        S.f0r[2][r][c] = sd.x * pavg; S.f0i[2][r][c] = sd.y * pavg;
    }
    __syncthreads();

    // ---- stage D: lconv1 + modReLU (region [-1, 17)) ----
    for (int t = tid; t < 18 * 18; t += 256) {
        int r = t / 18, c = t % 18;    // f0 idx = (r+1, c+1); x-local = (r+3, c+3)
        float vr[15], vi[15];
        #pragma unroll
        for (int i = 0; i < 3; i++) {
            vr[i] = S.f0r[i][r + 1][c + 1];
            vi[i] = S.f0i[i][r + 1][c + 1];
        }
        float2 l0 = S.lx[r + 3][c + 3], l1 = S.ly[r + 3][c + 3];
        float2 m0 = S.lx[r + 2][c + 3], m1 = S.ly[r + 3][c + 2];  // conj inline
        #pragma unroll
        for (int i = 0; i < 3; i++) {
            float fr, fi2;
            fr = S.f0r[i][r + 2][c + 1]; fi2 = S.f0i[i][r + 2][c + 1];
            vr[3 + i]  = l0.x * fr - l0.y * fi2;  vi[3 + i]  = l0.x * fi2 + l0.y * fr;
            fr = S.f0r[i][r + 1][c + 2]; fi2 = S.f0i[i][r + 1][c + 2];
            vr[6 + i]  = l1.x * fr - l1.y * fi2;  vi[6 + i]  = l1.x * fi2 + l1.y * fr;
            fr = S.f0r[i][r    ][c + 1]; fi2 = S.f0i[i][r    ][c + 1];
            vr[9 + i]  = m0.x * fr + m0.y * fi2;  vi[9 + i]  = m0.x * fi2 - m0.y * fr;
            fr = S.f0r[i][r + 1][c    ]; fi2 = S.f0i[i][r + 1][c    ];
            vr[12 + i] = m1.x * fr + m1.y * fi2;  vi[12 + i] = m1.x * fi2 - m1.y * fr;
        }
        u64 AR[8], AI[8];
        #pragma unroll
        for (int p = 0; p < 8; p++) { AR[p] = 0ull; AI[p] = 0ull; }
        #pragma unroll
        for (int k = 0; k < 15; k++) {
            u64 rr = pk2(vr[k], vr[k]);
            u64 ii = pk2(vi[k], vi[k]);
            #pragma unroll
            for (int p = 0; p < 8; p++) {
                u64 w = *reinterpret_cast<const u64*>(&CWc.wD[k][p][0]);
                AR[p] = ffma2(w, rr, AR[p]);
                AI[p] = ffma2(w, ii, AI[p]);
            }
        }
        #pragma unroll
        for (int p = 0; p < 8; p++) {
            float a0r, a1r, a0i, a1i;
            unpk2(AR[p], a0r, a1r);
            unpk2(AI[p], a0i, a1i);
            float m2a = fmaf(a0r, a0r, fmaf(a0i, a0i, 1e-12f));
            float m2b = fmaf(a1r, a1r, fmaf(a1i, a1i, 1e-12f));
            float q0 = rsqrtf(m2a), q1 = rsqrtf(m2b);
            float s0 = fmaxf(fmaf(CWc.b1[2 * p], q0, 1.f), 0.f);
            float s1 = fmaxf(fmaf(CWc.b1[2 * p + 1], q1, 1.f), 0.f);
            u64 S2 = pk2(s0, s1);
            *reinterpret_cast<u64*>(&S.g1r[r][c][2 * p]) = fmul2(AR[p], S2);
            *reinterpret_cast<u64*>(&S.g1i[r][c][2 * p]) = fmul2(AI[p], S2);
        }
    }
    __syncthreads();

    // ---- stage E: lconv2 + modReLU + readout (16x16 outputs) ----
    {
        int r = tid >> 4, c = tid & 15;   // g1 idx = (r+1, c+1); x-local = (r+4, c+4)
        u64 ACCr[8], ACCi[8];
        #pragma unroll
        for (int o = 0; o < 8; o++) { ACCr[o] = 0ull; ACCi[o] = 0ull; }

        // center tap (no link), chunked loads
        {
            const float* gr = &S.g1r[r + 1][c + 1][0];
            const float* gi = &S.g1i[r + 1][c + 1][0];
            #pragma unroll
            for (int ch = 0; ch < 2; ch++) {
                u64 vrp[4], vip[4];
                #pragma unroll
                for (int j = 0; j < 4; j++) {
                    vrp[j] = *reinterpret_cast<const u64*>(gr + 8 * ch + 2 * j);
                    vip[j] = *reinterpret_cast<const u64*>(gi + 8 * ch + 2 * j);
                }
                #pragma unroll
                for (int j = 0; j < 4; j++) {
                    #pragma unroll
                    for (int o = 0; o < 8; o++) {
                        u64 w = *reinterpret_cast<const u64*>(&CWc.c2[o][8 * ch + 2 * j]);
                        ACCr[o] = ffma2(w, vrp[j], ACCr[o]);
                        ACCi[o] = ffma2(w, vip[j], ACCi[o]);
                    }
                }
            }
        }
        float2 l0 = S.lx[r + 4][c + 4], l1 = S.ly[r + 4][c + 4];
        float2 m0 = S.lx[r + 3][c + 4], m1 = S.ly[r + 4][c + 3];
        tapE(&S.g1r[r + 2][c + 1][0], &S.g1i[r + 2][c + 1][0], CWc.fw2[0],  l0.x,  l0.y, ACCr, ACCi);
        tapE(&S.g1r[r + 1][c + 2][0], &S.g1i[r + 1][c + 2][0], CWc.fw2[1],  l1.x,  l1.y, ACCr, ACCi);
        tapE(&S.g1r[r    ][c + 1][0], &S.g1i[r    ][c + 1][0], CWc.bw2[0],  m0.x, -m0.y, ACCr, ACCi);
        tapE(&S.g1r[r + 1][c    ][0], &S.g1i[r + 1][c    ][0], CWc.bw2[1],  m1.x, -m1.y, ACCr, ACCi);

        float val = CWc.rob;
        #pragma unroll
        for (int o = 0; o < 8; o++) {
            float rl, rh, il, ih;
            unpk2(ACCr[o], rl, rh);
            unpk2(ACCi[o], il, ih);
            float ar = rl + rh, ai = il + ih;
            float m2 = fmaf(ar, ar, fmaf(ai, ai, 1e-12f));
            float q  = rsqrtf(m2);
            float sc = fmaxf(fmaf(CWc.b2[o], q, 1.f), 0.f);
            val = fmaf(CWc.ro[o], m2 * sc * sc, val);
        }
        out[(size_t)b * L * L + (ti + r) * L + (tj + c)] = val;
    }
}

extern "C" void kernel_launch(void* const* d_in, const int* in_sizes, int n_in,
                              void* d_out, int out_size) {
    const float* x   = (const float*)d_in[0];
    const float* c1  = (const float*)d_in[1];
    const float* fw1 = (const float*)d_in[2];
    const float* bw1 = (const float*)d_in[3];
    const float* b1  = (const float*)d_in[4];
    const float* c2  = (const float*)d_in[5];
    const float* fw2 = (const float*)d_in[6];
    const float* bw2 = (const float*)d_in[7];
    const float* b2  = (const float*)d_in[8];
    const float* row = (const float*)d_in[9];
    const float* rob = (const float*)d_in[10];
    float* out = (float*)d_out;
    (void)in_sizes; (void)n_in; (void)out_size;

    // node 1: seed + weight packing
    seed_kernel<<<65, 256>>>(x, c1, fw1, bw1, b1, c2, fw2, bw2, b2, row, rob);

    // node 2: one constant-bank upload (D2D, capture-legal)
    void* stage_ptr = nullptr;
    cudaGetSymbolAddress(&stage_ptr, g_stage);
    cudaMemcpyToSymbolAsync(CWc, stage_ptr, sizeof(CW), 0, cudaMemcpyDeviceToDevice);

    // node 3: fused main kernel
    cudaFuncSetAttribute(main_kernel, cudaFuncAttributeMaxDynamicSharedMemorySize,
                         (int)sizeof(Smem));
    dim3 grid(8, 8, BATCH);
    main_kernel<<<grid, 256, sizeof(Smem)>>>(x, out);
}

// round 6
// speedup vs baseline: 1.5199x; 1.0917x over previous
#include <cuda_runtime.h>

#define L 128
#define BATCH 64

typedef unsigned long long u64;

__device__ __forceinline__ float2 cmulf(float2 a, float2 b) {
    return make_float2(a.x*b.x - a.y*b.y, a.x*b.y + a.y*b.x);
}
__device__ __forceinline__ float2 conjf2(float2 a) { return make_float2(a.x, -a.y); }

__device__ __forceinline__ u64 pk2(float a, float b) {
    u64 r; asm("mov.b64 %0, {%1,%2};" : "=l"(r) : "f"(a), "f"(b)); return r;
}
__device__ __forceinline__ void unpk2(u64 v, float& a, float& b) {
    asm("mov.b64 {%0,%1}, %2;" : "=f"(a), "=f"(b) : "l"(v));
}
__device__ __forceinline__ u64 ffma2(u64 a, u64 b, u64 c) {
    u64 d; asm("fma.rn.f32x2 %0, %1, %2, %3;" : "=l"(d) : "l"(a), "l"(b), "l"(c)); return d;
}
__device__ __forceinline__ u64 fmul2(u64 a, u64 b) {
    u64 d; asm("mul.rn.f32x2 %0, %1, %2;" : "=l"(d) : "l"(a), "l"(b)); return d;
}

// ---------------- consolidated weight bank ----------------
struct CW {
    float wD[15][8][2];    // layer1 packed: [tap*3+i][o-pair][2]
    float c2[8][16];       // center2 raw
    float fw2[2][8][16];
    float bw2[2][8][16];
    float b1[16];
    float b2[8];
    float ro[8];
    float rob;
    float pad;
};
__constant__ CW CWc;
__device__ CW g_stage;                 // filled by seed_kernel block 64

// 8 MB scratch for the Wilson-seed (conjugated path), (B, L, L) complex
__device__ float2 g_seed[BATCH * L * L];

// ---------------------------------------------------------------------------
// Kernel 1: Wilson seed (blocks 0..63) + weight packing (block 64)
// ---------------------------------------------------------------------------
__global__ __launch_bounds__(256) void seed_kernel(
    const float* __restrict__ x,
    const float* __restrict__ c1, const float* __restrict__ fw1,
    const float* __restrict__ bw1, const float* __restrict__ b1,
    const float* __restrict__ c2, const float* __restrict__ fw2,
    const float* __restrict__ bw2, const float* __restrict__ b2,
    const float* __restrict__ ro, const float* __restrict__ rob)
{
    int b    = blockIdx.x;
    int tid  = threadIdx.x;

    if (b == 64) {
        if (tid < 120) {
            int k = tid / 8, p = tid % 8;
            int tap = k / 3, i = k % 3;
            const float* W;
            if      (tap == 0) W = c1;
            else if (tap == 1) W = fw1;
            else if (tap == 2) W = fw1 + 48;
            else if (tap == 3) W = bw1;
            else               W = bw1 + 48;
            g_stage.wD[k][p][0] = W[(2*p)*3 + i];
            g_stage.wD[k][p][1] = W[(2*p+1)*3 + i];
        }
        for (int t = tid; t < 128; t += 256) ((float*)g_stage.c2)[t]  = c2[t];
        if (tid < 256) {
            ((float*)g_stage.fw2)[tid] = fw2[tid];
            ((float*)g_stage.bw2)[tid] = bw2[tid];
        }
        if (tid < 16) g_stage.b1[tid] = b1[tid];
        if (tid < 8)  { g_stage.b2[tid] = b2[tid]; g_stage.ro[tid] = ro[tid]; }
        if (tid == 0) g_stage.rob = rob[0];
        return;
    }

    int w    = tid >> 5;
    int lane = tid & 31;
    __shared__ float2 s_ax[L];
    const float* X = x + (size_t)b * 4 * L * L;

    if (w == 0) {
        float2 u[4];
        #pragma unroll
        for (int t = 0; t < 4; t++) {
            int k = lane * 4 + t;
            u[t] = make_float2(X[0 * L * L + k * L], X[1 * L * L + k * L]);
        }
        float2 e1 = u[0];
        float2 e2 = cmulf(e1, u[1]);
        float2 e3 = cmulf(e2, u[2]);
        float2 v  = cmulf(e3, u[3]);
        #pragma unroll
        for (int off = 1; off < 32; off <<= 1) {
            float vx = __shfl_up_sync(0xffffffffu, v.x, off);
            float vy = __shfl_up_sync(0xffffffffu, v.y, off);
            if (lane >= off) v = cmulf(make_float2(vx, vy), v);
        }
        float wx = __shfl_up_sync(0xffffffffu, v.x, 1);
        float wy = __shfl_up_sync(0xffffffffu, v.y, 1);
        float2 W = (lane == 0) ? make_float2(1.f, 0.f) : make_float2(wx, wy);
        s_ax[lane * 4 + 0] = W;
        s_ax[lane * 4 + 1] = cmulf(W, e1);
        s_ax[lane * 4 + 2] = cmulf(W, e2);
        s_ax[lane * 4 + 3] = cmulf(W, e3);
    }
    __syncthreads();

    float2* seed = g_seed + b * L * L;
    for (int i = w; i < L; i += 8) {
        const float4* pr = reinterpret_cast<const float4*>(X + 2 * L * L + i * L);
        const float4* pi = reinterpret_cast<const float4*>(X + 3 * L * L + i * L);
        float4 r4 = pr[lane], i4 = pi[lane];
        float2 u0 = make_float2(r4.x, i4.x);
        float2 u1 = make_float2(r4.y, i4.y);
        float2 u2 = make_float2(r4.z, i4.z);
        float2 u3 = make_float2(r4.w, i4.w);
        float2 e1 = u0;
        float2 e2 = cmulf(e1, u1);
        float2 e3 = cmulf(e2, u2);
        float2 v  = cmulf(e3, u3);
        #pragma unroll
        for (int off = 1; off < 32; off <<= 1) {
            float vx = __shfl_up_sync(0xffffffffu, v.x, off);
            float vy = __shfl_up_sync(0xffffffffu, v.y, off);
            if (lane >= off) v = cmulf(make_float2(vx, vy), v);
        }
        float wx = __shfl_up_sync(0xffffffffu, v.x, 1);
        float wy = __shfl_up_sync(0xffffffffu, v.y, 1);
        float2 W = (lane == 0) ? make_float2(1.f, 0.f) : make_float2(wx, wy);
        float2 base = cmulf(s_ax[i], W);
        float2 p0 = base;
        float2 p1 = cmulf(base, e1);
        float2 p2 = cmulf(base, e2);
        float2 p3 = cmulf(base, e3);
        float4* dst = reinterpret_cast<float4*>(seed + i * L + lane * 4);
        dst[0] = make_float4(p0.x, -p0.y, p1.x, -p1.y);
        dst[1] = make_float4(p2.x, -p2.y, p3.x, -p3.y);
    }
}

// ---------------------------------------------------------------------------
// Kernel 2: fused main kernel
// ---------------------------------------------------------------------------
struct Smem {
    float2 lx[24][25];        // ux, region [-4, 20)
    float2 ly[24][25];        // uy
    float  pc[22][23];        // cos(plaquette), region [-3, 19)
    float  sdr[20][21];       // seed real, region [-2, 18)
    float  sdi[20][21];       // seed imag
    float  pavg[20][21];      // plaquette 5-avg
    alignas(16) float g1r[18][19][20];   // layer-1 activations SoA [row][col][ch16+pad4]
    alignas(16) float g1i[18][19][20];
};

// layer-2 tap: accumulate  link * (W @ g(neighbor)) with LDS.128 feature loads
__device__ __forceinline__ void tapE(const float* __restrict__ gr,
                                     const float* __restrict__ gi,
                                     const float (&W)[8][16],
                                     float tx, float ty,
                                     u64* ACCr, u64* ACCi) {
    u64 TAr[8], TAi[8];
    #pragma unroll
    for (int o = 0; o < 8; o++) { TAr[o] = 0ull; TAi[o] = 0ull; }
    #pragma unroll
    for (int q = 0; q < 4; q++) {
        longlong2 vr = *reinterpret_cast<const longlong2*>(gr + 4 * q);
        longlong2 vi = *reinterpret_cast<const longlong2*>(gi + 4 * q);
        #pragma unroll
        for (int o = 0; o < 8; o++) {
            u64 wa = *reinterpret_cast<const u64*>(&W[o][4 * q]);
            u64 wb = *reinterpret_cast<const u64*>(&W[o][4 * q + 2]);
            TAr[o] = ffma2(wa, (u64)vr.x, TAr[o]);
            TAr[o] = ffma2(wb, (u64)vr.y, TAr[o]);
            TAi[o] = ffma2(wa, (u64)vi.x, TAi[o]);
            TAi[o] = ffma2(wb, (u64)vi.y, TAi[o]);
        }
    }
    u64 txx = pk2(tx, tx), tyy = pk2(ty, ty), nty = pk2(-ty, -ty);
    #pragma unroll
    for (int o = 0; o < 8; o++) {
        ACCr[o] = ffma2(txx, TAr[o], ffma2(nty, TAi[o], ACCr[o]));
        ACCi[o] = ffma2(txx, TAi[o], ffma2(tyy, TAr[o], ACCi[o]));
    }
}

__global__ __launch_bounds__(256, 3) void main_kernel(
    const float* __restrict__ x, float* __restrict__ out)
{
    extern __shared__ unsigned char smem_raw[];
    Smem& S = *reinterpret_cast<Smem*>(smem_raw);
    int tid = threadIdx.x;
    int b   = blockIdx.z;
    int ti  = blockIdx.y * 16;
    int tj  = blockIdx.x * 16;
    const float* X = x + (size_t)b * 4 * L * L;

    // ---- stage A: link halo (region [-4, 20)) ----
    for (int t = tid; t < 24 * 24; t += 256) {
        int r = t / 24, c = t % 24;
        int gi = (ti + r - 4) & 127, gj = (tj + c - 4) & 127;
        int base = gi * L + gj;
        S.lx[r][c] = make_float2(X[base],             X[L * L + base]);
        S.ly[r][c] = make_float2(X[2 * L * L + base], X[3 * L * L + base]);
    }
    __syncthreads();

    // ---- stage B: cos(plaquette) (region [-3, 19)) ----
    for (int t = tid; t < 22 * 22; t += 256) {
        int r = t / 22, c = t % 22;
        float2 p = cmulf(S.lx[r + 1][c + 1], S.ly[r + 2][c + 1]);
        p = cmulf(p, conjf2(S.lx[r + 1][c + 2]));
        p = cmulf(p, conjf2(S.ly[r + 1][c + 1]));
        float n = p.x * p.x + p.y * p.y;
        S.pc[r][c] = p.x * rsqrtf(fmaxf(n, 1e-38f));
    }
    __syncthreads();

    // ---- stage C: seed + pavg (region [-2, 18)) ----
    const float2* seed = g_seed + b * L * L;
    for (int t = tid; t < 20 * 20; t += 256) {
        int r = t / 20, c = t % 20;
        int gi = (ti + r - 2) & 127, gj = (tj + c - 2) & 127;
        float2 sd = seed[gi * L + gj];
        float pcc  = S.pc[r + 1][c + 1];
        float pavg = 0.2f * (pcc + S.pc[r][c + 1] + S.pc[r + 2][c + 1]
                                 + S.pc[r + 1][c] + S.pc[r + 1][c + 2]);
        S.sdr[r][c]  = sd.x;
        S.sdi[r][c]  = sd.y;
        S.pavg[r][c] = pavg;
    }
    __syncthreads();

    // ---- stage D: lconv1 (factorized) + modReLU (region [-1, 17)) ----
    // out[o] = sum_tap T_tap * (w0[o] + w1[o]*pc_sh + w2[o]*pavg_sh)
    for (int t = tid; t < 18 * 18; t += 256) {
        int r = t / 18, c = t % 18;    // site f0-idx = (r+1, c+1); x-local = (r+3, c+3)
        float2 l0 = S.lx[r + 3][c + 3], l1 = S.ly[r + 3][c + 3];
        float2 m0 = S.lx[r + 2][c + 3], m1 = S.ly[r + 3][c + 2];

        float Tr[5], Ti[5], PCv[5], PAv[5];
        // center (r+1, c+1)
        Tr[0] = S.sdr[r + 1][c + 1]; Ti[0] = S.sdi[r + 1][c + 1];
        PCv[0] = S.pc[r + 2][c + 2]; PAv[0] = S.pavg[r + 1][c + 1];
        // fwd mu=0 (r+2, c+1): l0 * sd
        {
            float sr = S.sdr[r + 2][c + 1], si = S.sdi[r + 2][c + 1];
            Tr[1] = l0.x * sr - l0.y * si; Ti[1] = l0.x * si + l0.y * sr;
            PCv[1] = S.pc[r + 3][c + 2]; PAv[1] = S.pavg[r + 2][c + 1];
        }
        // fwd mu=1 (r+1, c+2): l1 * sd
        {
            float sr = S.sdr[r + 1][c + 2], si = S.sdi[r + 1][c + 2];
            Tr[2] = l1.x * sr - l1.y * si; Ti[2] = l1.x * si + l1.y * sr;
            PCv[2] = S.pc[r + 2][c + 3]; PAv[2] = S.pavg[r + 1][c + 2];
        }
        // bwd mu=0 (r, c+1): conj(m0) * sd
        {
            float sr = S.sdr[r][c + 1], si = S.sdi[r][c + 1];
            Tr[3] = m0.x * sr + m0.y * si; Ti[3] = m0.x * si - m0.y * sr;
            PCv[3] = S.pc[r + 1][c + 2]; PAv[3] = S.pavg[r][c + 1];
        }
        // bwd mu=1 (r+1, c): conj(m1) * sd
        {
            float sr = S.sdr[r + 1][c], si = S.sdi[r + 1][c];
            Tr[4] = m1.x * sr + m1.y * si; Ti[4] = m1.x * si - m1.y * sr;
            PCv[4] = S.pc[r + 2][c + 1]; PAv[4] = S.pavg[r + 1][c];
        }

        u64 AR[8], AI[8];
        #pragma unroll
        for (int p = 0; p < 8; p++) { AR[p] = 0ull; AI[p] = 0ull; }
        #pragma unroll
        for (int tap = 0; tap < 5; tap++) {
            u64 pc2 = pk2(PCv[tap], PCv[tap]);
            u64 pa2 = pk2(PAv[tap], PAv[tap]);
            u64 trr = pk2(Tr[tap], Tr[tap]);
            u64 tii = pk2(Ti[tap], Ti[tap]);
            #pragma unroll
            for (int p = 0; p < 8; p++) {
                u64 w0 = *reinterpret_cast<const u64*>(&CWc.wD[tap * 3 + 0][p][0]);
                u64 w1 = *reinterpret_cast<const u64*>(&CWc.wD[tap * 3 + 1][p][0]);
                u64 w2 = *reinterpret_cast<const u64*>(&CWc.wD[tap * 3 + 2][p][0]);
                u64 a = ffma2(pa2, w2, ffma2(pc2, w1, w0));
                AR[p] = ffma2(a, trr, AR[p]);
                AI[p] = ffma2(a, tii, AI[p]);
            }
        }
        #pragma unroll
        for (int p = 0; p < 8; p++) {
            float a0r, a1r, a0i, a1i;
            unpk2(AR[p], a0r, a1r);
            unpk2(AI[p], a0i, a1i);
            float m2a = fmaf(a0r, a0r, fmaf(a0i, a0i, 1e-12f));
            float m2b = fmaf(a1r, a1r, fmaf(a1i, a1i, 1e-12f));
            float q0 = rsqrtf(m2a), q1 = rsqrtf(m2b);
            float s0 = fmaxf(fmaf(CWc.b1[2 * p], q0, 1.f), 0.f);
            float s1 = fmaxf(fmaf(CWc.b1[2 * p + 1], q1, 1.f), 0.f);
            u64 S2 = pk2(s0, s1);
            *reinterpret_cast<u64*>(&S.g1r[r][c][2 * p]) = fmul2(AR[p], S2);
            *reinterpret_cast<u64*>(&S.g1i[r][c][2 * p]) = fmul2(AI[p], S2);
        }
    }
    __syncthreads();

    // ---- stage E: lconv2 + modReLU + readout (16x16 outputs) ----
    {
        int r = tid >> 4, c = tid & 15;   // g1 idx = (r+1, c+1); x-local = (r+4, c+4)
        u64 ACCr[8], ACCi[8];
        #pragma unroll
        for (int o = 0; o < 8; o++) { ACCr[o] = 0ull; ACCi[o] = 0ull; }

        // center tap (no link), LDS.128 loads
        {
            const float* gr = &S.g1r[r + 1][c + 1][0];
            const float* gi = &S.g1i[r + 1][c + 1][0];
            #pragma unroll
            for (int q = 0; q < 4; q++) {
                longlong2 vr = *reinterpret_cast<const longlong2*>(gr + 4 * q);
                longlong2 vi = *reinterpret_cast<const longlong2*>(gi + 4 * q);
                #pragma unroll
                for (int o = 0; o < 8; o++) {
                    u64 wa = *reinterpret_cast<const u64*>(&CWc.c2[o][4 * q]);
                    u64 wb = *reinterpret_cast<const u64*>(&CWc.c2[o][4 * q + 2]);
                    ACCr[o] = ffma2(wa, (u64)vr.x, ACCr[o]);
                    ACCr[o] = ffma2(wb, (u64)vr.y, ACCr[o]);
                    ACCi[o] = ffma2(wa, (u64)vi.x, ACCi[o]);
                    ACCi[o] = ffma2(wb, (u64)vi.y, ACCi[o]);
                }
            }
        }
        float2 l0 = S.lx[r + 4][c + 4], l1 = S.ly[r + 4][c + 4];
        float2 m0 = S.lx[r + 3][c + 4], m1 = S.ly[r + 4][c + 3];
        tapE(&S.g1r[r + 2][c + 1][0], &S.g1i[r + 2][c + 1][0], CWc.fw2[0],  l0.x,  l0.y, ACCr, ACCi);
        tapE(&S.g1r[r + 1][c + 2][0], &S.g1i[r + 1][c + 2][0], CWc.fw2[1],  l1.x,  l1.y, ACCr, ACCi);
        tapE(&S.g1r[r    ][c + 1][0], &S.g1i[r    ][c + 1][0], CWc.bw2[0],  m0.x, -m0.y, ACCr, ACCi);
        tapE(&S.g1r[r + 1][c    ][0], &S.g1i[r + 1][c    ][0], CWc.bw2[1],  m1.x, -m1.y, ACCr, ACCi);

        float val = CWc.rob;
        #pragma unroll
        for (int o = 0; o < 8; o++) {
            float rl, rh, il, ih;
            unpk2(ACCr[o], rl, rh);
            unpk2(ACCi[o], il, ih);
            float ar = rl + rh, ai = il + ih;
            float m2 = fmaf(ar, ar, fmaf(ai, ai, 1e-12f));
            float q  = rsqrtf(m2);
            float sc = fmaxf(fmaf(CWc.b2[o], q, 1.f), 0.f);
            val = fmaf(CWc.ro[o], m2 * sc * sc, val);
        }
        out[(size_t)b * L * L + (ti + r) * L + (tj + c)] = val;
    }
}

extern "C" void kernel_launch(void* const* d_in, const int* in_sizes, int n_in,
                              void* d_out, int out_size) {
    const float* x   = (const float*)d_in[0];
    const float* c1  = (const float*)d_in[1];
    const float* fw1 = (const float*)d_in[2];
    const float* bw1 = (const float*)d_in[3];
    const float* b1  = (const float*)d_in[4];
    const float* c2  = (const float*)d_in[5];
    const float* fw2 = (const float*)d_in[6];
    const float* bw2 = (const float*)d_in[7];
    const float* b2  = (const float*)d_in[8];
    const float* row = (const float*)d_in[9];
    const float* rob = (const float*)d_in[10];
    float* out = (float*)d_out;
    (void)in_sizes; (void)n_in; (void)out_size;

    // node 1: seed + weight packing
    seed_kernel<<<65, 256>>>(x, c1, fw1, bw1, b1, c2, fw2, bw2, b2, row, rob);

    // node 2: one constant-bank upload (D2D, capture-legal)
    void* stage_ptr = nullptr;
    cudaGetSymbolAddress(&stage_ptr, g_stage);
    cudaMemcpyToSymbolAsync(CWc, stage_ptr, sizeof(CW), 0, cudaMemcpyDeviceToDevice);

    // node 3: fused main kernel
    cudaFuncSetAttribute(main_kernel, cudaFuncAttributeMaxDynamicSharedMemorySize,
                         (int)sizeof(Smem));
    dim3 grid(8, 8, BATCH);
    main_kernel<<<grid, 256, sizeof(Smem)>>>(x, out);
}

// round 9
// speedup vs baseline: 1.7943x; 1.1805x over previous
#include <cuda_runtime.h>

#define L 128
#define BATCH 64

typedef unsigned long long u64;

__device__ __forceinline__ float2 cmulf(float2 a, float2 b) {
    return make_float2(a.x*b.x - a.y*b.y, a.x*b.y + a.y*b.x);
}
__device__ __forceinline__ float2 conjf2(float2 a) { return make_float2(a.x, -a.y); }

__device__ __forceinline__ u64 pk2(float a, float b) {
    u64 r; asm("mov.b64 %0, {%1,%2};" : "=l"(r) : "f"(a), "f"(b)); return r;
}
__device__ __forceinline__ void unpk2(u64 v, float& a, float& b) {
    asm("mov.b64 {%0,%1}, %2;" : "=f"(a), "=f"(b) : "l"(v));
}
__device__ __forceinline__ u64 ffma2(u64 a, u64 b, u64 c) {
    u64 d; asm("fma.rn.f32x2 %0, %1, %2, %3;" : "=l"(d) : "l"(a), "l"(b), "l"(c)); return d;
}
__device__ __forceinline__ u64 fmul2(u64 a, u64 b) {
    u64 d; asm("mul.rn.f32x2 %0, %1, %2;" : "=l"(d) : "l"(a), "l"(b)); return d;
}

// ---------------- consolidated weight bank ----------------
struct CW {
    float wD[15][8][2];    // layer1 packed: [tap*3+i][o-pair][2]
    float c2[8][16];       // center2 raw
    float fw2[2][8][16];
    float bw2[2][8][16];
    float b1[16];
    float b2[8];
    float ro[8];
    float rob;
    int   bz1;             // 1 if bias1 is all-zero -> modReLU1 is identity
    int   bz2;             // 1 if bias2 is all-zero -> modReLU2 is identity
    int   pad;
};
__constant__ CW CWc;
__device__ CW g_stage;                 // filled by seed_kernel block 64

// 8 MB scratch for the Wilson-seed (conjugated path), (B, L, L) complex
__device__ float2 g_seed[BATCH * L * L];

// ---------------------------------------------------------------------------
// Kernel 1: Wilson seed (blocks 0..63) + weight packing (block 64)
// ---------------------------------------------------------------------------
__global__ __launch_bounds__(256) void seed_kernel(
    const float* __restrict__ x,
    const float* __restrict__ c1, const float* __restrict__ fw1,
    const float* __restrict__ bw1, const float* __restrict__ b1,
    const float* __restrict__ c2, const float* __restrict__ fw2,
    const float* __restrict__ bw2, const float* __restrict__ b2,
    const float* __restrict__ ro, const float* __restrict__ rob)
{
    int b    = blockIdx.x;
    int tid  = threadIdx.x;

    if (b == 64) {
        if (tid < 120) {
            int k = tid / 8, p = tid % 8;
            int tap = k / 3, i = k % 3;
            const float* W;
            if      (tap == 0) W = c1;
            else if (tap == 1) W = fw1;
            else if (tap == 2) W = fw1 + 48;
            else if (tap == 3) W = bw1;
            else               W = bw1 + 48;
            g_stage.wD[k][p][0] = W[(2*p)*3 + i];
            g_stage.wD[k][p][1] = W[(2*p+1)*3 + i];
        }
        for (int t = tid; t < 128; t += 256) ((float*)g_stage.c2)[t]  = c2[t];
        if (tid < 256) {
            ((float*)g_stage.fw2)[tid] = fw2[tid];
            ((float*)g_stage.bw2)[tid] = bw2[tid];
        }
        if (tid < 16) g_stage.b1[tid] = b1[tid];
        if (tid < 8)  { g_stage.b2[tid] = b2[tid]; g_stage.ro[tid] = ro[tid]; }
        if (tid == 0) {
            g_stage.rob = rob[0];
            int z1 = 1, z2 = 1;
            for (int i = 0; i < 16; i++) if (b1[i] != 0.f) z1 = 0;
            for (int i = 0; i < 8;  i++) if (b2[i] != 0.f) z2 = 0;
            g_stage.bz1 = z1;
            g_stage.bz2 = z2;
        }
        return;
    }

    int w    = tid >> 5;
    int lane = tid & 31;
    __shared__ float2 s_ax[L];
    const float* X = x + (size_t)b * 4 * L * L;

    if (w == 0) {
        float2 u[4];
        #pragma unroll
        for (int t = 0; t < 4; t++) {
            int k = lane * 4 + t;
            u[t] = make_float2(X[0 * L * L + k * L], X[1 * L * L + k * L]);
        }
        float2 e1 = u[0];
        float2 e2 = cmulf(e1, u[1]);
        float2 e3 = cmulf(e2, u[2]);
        float2 v  = cmulf(e3, u[3]);
        #pragma unroll
        for (int off = 1; off < 32; off <<= 1) {
            float vx = __shfl_up_sync(0xffffffffu, v.x, off);
            float vy = __shfl_up_sync(0xffffffffu, v.y, off);
            if (lane >= off) v = cmulf(make_float2(vx, vy), v);
        }
        float wx = __shfl_up_sync(0xffffffffu, v.x, 1);
        float wy = __shfl_up_sync(0xffffffffu, v.y, 1);
        float2 W = (lane == 0) ? make_float2(1.f, 0.f) : make_float2(wx, wy);
        s_ax[lane * 4 + 0] = W;
        s_ax[lane * 4 + 1] = cmulf(W, e1);
        s_ax[lane * 4 + 2] = cmulf(W, e2);
        s_ax[lane * 4 + 3] = cmulf(W, e3);
    }
    __syncthreads();

    float2* seed = g_seed + b * L * L;
    for (int i = w; i < L; i += 8) {
        const float4* pr = reinterpret_cast<const float4*>(X + 2 * L * L + i * L);
        const float4* pi = reinterpret_cast<const float4*>(X + 3 * L * L + i * L);
        float4 r4 = pr[lane], i4 = pi[lane];
        float2 u0 = make_float2(r4.x, i4.x);
        float2 u1 = make_float2(r4.y, i4.y);
        float2 u2 = make_float2(r4.z, i4.z);
        float2 u3 = make_float2(r4.w, i4.w);
        float2 e1 = u0;
        float2 e2 = cmulf(e1, u1);
        float2 e3 = cmulf(e2, u2);
        float2 v  = cmulf(e3, u3);
        #pragma unroll
        for (int off = 1; off < 32; off <<= 1) {
            float vx = __shfl_up_sync(0xffffffffu, v.x, off);
            float vy = __shfl_up_sync(0xffffffffu, v.y, off);
            if (lane >= off) v = cmulf(make_float2(vx, vy), v);
        }
        float wx = __shfl_up_sync(0xffffffffu, v.x, 1);
        float wy = __shfl_up_sync(0xffffffffu, v.y, 1);
        float2 W = (lane == 0) ? make_float2(1.f, 0.f) : make_float2(wx, wy);
        float2 base = cmulf(s_ax[i], W);
        float2 p0 = base;
        float2 p1 = cmulf(base, e1);
        float2 p2 = cmulf(base, e2);
        float2 p3 = cmulf(base, e3);
        float4* dst = reinterpret_cast<float4*>(seed + i * L + lane * 4);
        dst[0] = make_float4(p0.x, -p0.y, p1.x, -p1.y);
        dst[1] = make_float4(p2.x, -p2.y, p3.x, -p3.y);
    }
}

// ---------------------------------------------------------------------------
// Kernel 2: fused main kernel
// ---------------------------------------------------------------------------
struct Smem {
    float2 lx[24][25];        // ux, region [-4, 20)
    float2 ly[24][25];        // uy
    float  pc[22][23];        // cos(plaquette), region [-3, 19)
    float  sdr[20][21];       // seed real, region [-2, 18)
    float  sdi[20][21];       // seed imag
    float  pavg[20][21];      // plaquette 5-avg
    alignas(16) float g1r[18][19][20];   // layer-1 activations SoA [row][col][ch16+pad4]
    alignas(16) float g1i[18][19][20];
};

// layer-2 tap: accumulate  link * (W @ g(neighbor)) with LDS.128 feature loads
__device__ __forceinline__ void tapE(const float* __restrict__ gr,
                                     const float* __restrict__ gi,
                                     const float (&W)[8][16],
                                     float tx, float ty,
                                     u64* ACCr, u64* ACCi) {
    u64 TAr[8], TAi[8];
    #pragma unroll
    for (int o = 0; o < 8; o++) { TAr[o] = 0ull; TAi[o] = 0ull; }
    #pragma unroll
    for (int q = 0; q < 4; q++) {
        longlong2 vr = *reinterpret_cast<const longlong2*>(gr + 4 * q);
        longlong2 vi = *reinterpret_cast<const longlong2*>(gi + 4 * q);
        #pragma unroll
        for (int o = 0; o < 8; o++) {
            u64 wa = *reinterpret_cast<const u64*>(&W[o][4 * q]);
            u64 wb = *reinterpret_cast<const u64*>(&W[o][4 * q + 2]);
            TAr[o] = ffma2(wa, (u64)vr.x, TAr[o]);
            TAr[o] = ffma2(wb, (u64)vr.y, TAr[o]);
            TAi[o] = ffma2(wa, (u64)vi.x, TAi[o]);
            TAi[o] = ffma2(wb, (u64)vi.y, TAi[o]);
        }
    }
    u64 txx = pk2(tx, tx), tyy = pk2(ty, ty), nty = pk2(-ty, -ty);
    #pragma unroll
    for (int o = 0; o < 8; o++) {
        ACCr[o] = ffma2(txx, TAr[o], ffma2(nty, TAi[o], ACCr[o]));
        ACCi[o] = ffma2(txx, TAi[o], ffma2(tyy, TAr[o], ACCi[o]));
    }
}

__global__ __launch_bounds__(256, 3) void main_kernel(
    const float* __restrict__ x, float* __restrict__ out)
{
    extern __shared__ unsigned char smem_raw[];
    Smem& S = *reinterpret_cast<Smem*>(smem_raw);
    int tid = threadIdx.x;
    int b   = blockIdx.z;
    int ti  = blockIdx.y * 16;
    int tj  = blockIdx.x * 16;
    const float* X = x + (size_t)b * 4 * L * L;

    // ---- stage A: link halo (region [-4, 20)) ----
    for (int t = tid; t < 24 * 24; t += 256) {
        int r = t / 24, c = t % 24;
        int gi = (ti + r - 4) & 127, gj = (tj + c - 4) & 127;
        int base = gi * L + gj;
        S.lx[r][c] = make_float2(X[base],             X[L * L + base]);
        S.ly[r][c] = make_float2(X[2 * L * L + base], X[3 * L * L + base]);
    }
    __syncthreads();

    // ---- stage B: cos(plaquette) (region [-3, 19)) ----
    for (int t = tid; t < 22 * 22; t += 256) {
        int r = t / 22, c = t % 22;
        float2 p = cmulf(S.lx[r + 1][c + 1], S.ly[r + 2][c + 1]);
        p = cmulf(p, conjf2(S.lx[r + 1][c + 2]));
        p = cmulf(p, conjf2(S.ly[r + 1][c + 1]));
        float n = p.x * p.x + p.y * p.y;
        S.pc[r][c] = p.x * rsqrtf(fmaxf(n, 1e-38f));
    }
    __syncthreads();

    // ---- stage C: seed + pavg (region [-2, 18)) ----
    const float2* seed = g_seed + b * L * L;
    for (int t = tid; t < 20 * 20; t += 256) {
        int r = t / 20, c = t % 20;
        int gi = (ti + r - 2) & 127, gj = (tj + c - 2) & 127;
        float2 sd = seed[gi * L + gj];
        float pcc  = S.pc[r + 1][c + 1];
        float pavg = 0.2f * (pcc + S.pc[r][c + 1] + S.pc[r + 2][c + 1]
                                 + S.pc[r + 1][c] + S.pc[r + 1][c + 2]);
        S.sdr[r][c]  = sd.x;
        S.sdi[r][c]  = sd.y;
        S.pavg[r][c] = pavg;
    }
    __syncthreads();

    // ---- stage D: lconv1 (factorized) + modReLU (region [-1, 17)) ----
    // out[o] = sum_tap T_tap * (w0[o] + w1[o]*pc_sh + w2[o]*pavg_sh)
    bool bz1 = (CWc.bz1 != 0);
    for (int t = tid; t < 18 * 18; t += 256) {
        int r = t / 18, c = t % 18;    // site f0-idx = (r+1, c+1); x-local = (r+3, c+3)
        float2 l0 = S.lx[r + 3][c + 3], l1 = S.ly[r + 3][c + 3];
        float2 m0 = S.lx[r + 2][c + 3], m1 = S.ly[r + 3][c + 2];

        float Tr[5], Ti[5], PCv[5], PAv[5];
        Tr[0] = S.sdr[r + 1][c + 1]; Ti[0] = S.sdi[r + 1][c + 1];
        PCv[0] = S.pc[r + 2][c + 2]; PAv[0] = S.pavg[r + 1][c + 1];
        {
            float sr = S.sdr[r + 2][c + 1], si = S.sdi[r + 2][c + 1];
            Tr[1] = l0.x * sr - l0.y * si; Ti[1] = l0.x * si + l0.y * sr;
            PCv[1] = S.pc[r + 3][c + 2]; PAv[1] = S.pavg[r + 2][c + 1];
        }
        {
            float sr = S.sdr[r + 1][c + 2], si = S.sdi[r + 1][c + 2];
            Tr[2] = l1.x * sr - l1.y * si; Ti[2] = l1.x * si + l1.y * sr;
            PCv[2] = S.pc[r + 2][c + 3]; PAv[2] = S.pavg[r + 1][c + 2];
        }
        {
            float sr = S.sdr[r][c + 1], si = S.sdi[r][c + 1];
            Tr[3] = m0.x * sr + m0.y * si; Ti[3] = m0.x * si - m0.y * sr;
            PCv[3] = S.pc[r + 1][c + 2]; PAv[3] = S.pavg[r][c + 1];
        }
        {
            float sr = S.sdr[r + 1][c], si = S.sdi[r + 1][c];
            Tr[4] = m1.x * sr + m1.y * si; Ti[4] = m1.x * si - m1.y * sr;
            PCv[4] = S.pc[r + 2][c + 1]; PAv[4] = S.pavg[r + 1][c];
        }

        u64 AR[8], AI[8];
        #pragma unroll
        for (int p = 0; p < 8; p++) { AR[p] = 0ull; AI[p] = 0ull; }
        #pragma unroll
        for (int tap = 0; tap < 5; tap++) {
            u64 pc2 = pk2(PCv[tap], PCv[tap]);
            u64 pa2 = pk2(PAv[tap], PAv[tap]);
            u64 trr = pk2(Tr[tap], Tr[tap]);
            u64 tii = pk2(Ti[tap], Ti[tap]);
            #pragma unroll
            for (int p = 0; p < 8; p++) {
                u64 w0 = *reinterpret_cast<const u64*>(&CWc.wD[tap * 3 + 0][p][0]);
                u64 w1 = *reinterpret_cast<const u64*>(&CWc.wD[tap * 3 + 1][p][0]);
                u64 w2 = *reinterpret_cast<const u64*>(&CWc.wD[tap * 3 + 2][p][0]);
                u64 a = ffma2(pa2, w2, ffma2(pc2, w1, w0));
                AR[p] = ffma2(a, trr, AR[p]);
                AI[p] = ffma2(a, tii, AI[p]);
            }
        }
        if (bz1) {
            // bias1 == 0 -> modReLU is exactly identity
            #pragma unroll
            for (int p = 0; p < 8; p++) {
                *reinterpret_cast<u64*>(&S.g1r[r][c][2 * p]) = AR[p];
                *reinterpret_cast<u64*>(&S.g1i[r][c][2 * p]) = AI[p];
            }
        } else {
            #pragma unroll
            for (int p = 0; p < 8; p++) {
                float a0r, a1r, a0i, a1i;
                unpk2(AR[p], a0r, a1r);
                unpk2(AI[p], a0i, a1i);
                float m2a = fmaf(a0r, a0r, fmaf(a0i, a0i, 1e-12f));
                float m2b = fmaf(a1r, a1r, fmaf(a1i, a1i, 1e-12f));
                float q0 = rsqrtf(m2a), q1 = rsqrtf(m2b);
                float s0 = fmaxf(fmaf(CWc.b1[2 * p], q0, 1.f), 0.f);
                float s1 = fmaxf(fmaf(CWc.b1[2 * p + 1], q1, 1.f), 0.f);
                u64 S2 = pk2(s0, s1);
                *reinterpret_cast<u64*>(&S.g1r[r][c][2 * p]) = fmul2(AR[p], S2);
                *reinterpret_cast<u64*>(&S.g1i[r][c][2 * p]) = fmul2(AI[p], S2);
            }
        }
    }
    __syncthreads();

    // ---- stage E: lconv2 + modReLU + readout (16x16 outputs) ----
    {
        int r = tid >> 4, c = tid & 15;   // g1 idx = (r+1, c+1); x-local = (r+4, c+4)
        u64 ACCr[8], ACCi[8];
        #pragma unroll
        for (int o = 0; o < 8; o++) { ACCr[o] = 0ull; ACCi[o] = 0ull; }

        // center tap (no link), LDS.128 loads
        {
            const float* gr = &S.g1r[r + 1][c + 1][0];
            const float* gi = &S.g1i[r + 1][c + 1][0];
            #pragma unroll
            for (int q = 0; q < 4; q++) {
                longlong2 vr = *reinterpret_cast<const longlong2*>(gr + 4 * q);
                longlong2 vi = *reinterpret_cast<const longlong2*>(gi + 4 * q);
                #pragma unroll
                for (int o = 0; o < 8; o++) {
                    u64 wa = *reinterpret_cast<const u64*>(&CWc.c2[o][4 * q]);
                    u64 wb = *reinterpret_cast<const u64*>(&CWc.c2[o][4 * q + 2]);
                    ACCr[o] = ffma2(wa, (u64)vr.x, ACCr[o]);
                    ACCr[o] = ffma2(wb, (u64)vr.y, ACCr[o]);
                    ACCi[o] = ffma2(wa, (u64)vi.x, ACCi[o]);
                    ACCi[o] = ffma2(wb, (u64)vi.y, ACCi[o]);
                }
            }
        }
        float2 l0 = S.lx[r + 4][c + 4], l1 = S.ly[r + 4][c + 4];
        float2 m0 = S.lx[r + 3][c + 4], m1 = S.ly[r + 4][c + 3];
        tapE(&S.g1r[r + 2][c + 1][0], &S.g1i[r + 2][c + 1][0], CWc.fw2[0],  l0.x,  l0.y, ACCr, ACCi);
        tapE(&S.g1r[r + 1][c + 2][0], &S.g1i[r + 1][c + 2][0], CWc.fw2[1],  l1.x,  l1.y, ACCr, ACCi);
        tapE(&S.g1r[r    ][c + 1][0], &S.g1i[r    ][c + 1][0], CWc.bw2[0],  m0.x, -m0.y, ACCr, ACCi);
        tapE(&S.g1r[r + 1][c    ][0], &S.g1i[r + 1][c    ][0], CWc.bw2[1],  m1.x, -m1.y, ACCr, ACCi);

        float val = CWc.rob;
        if (CWc.bz2 != 0) {
            // bias2 == 0 -> scale is exactly 1; inv = m2 directly
            #pragma unroll
            for (int o = 0; o < 8; o++) {
                float rl, rh, il, ih;
                unpk2(ACCr[o], rl, rh);
                unpk2(ACCi[o], il, ih);
                float ar = rl + rh, ai = il + ih;
                float m2 = fmaf(ar, ar, fmaf(ai, ai, 1e-12f));
                val = fmaf(CWc.ro[o], m2, val);
            }
        } else {
            #pragma unroll
            for (int o = 0; o < 8; o++) {
                float rl, rh, il, ih;
                unpk2(ACCr[o], rl, rh);
                unpk2(ACCi[o], il, ih);
                float ar = rl + rh, ai = il + ih;
                float m2 = fmaf(ar, ar, fmaf(ai, ai, 1e-12f));
                float q  = rsqrtf(m2);
                float sc = fmaxf(fmaf(CWc.b2[o], q, 1.f), 0.f);
                val = fmaf(CWc.ro[o], m2 * sc * sc, val);
            }
        }
        out[(size_t)b * L * L + (ti + r) * L + (tj + c)] = val;
    }
}

extern "C" void kernel_launch(void* const* d_in, const int* in_sizes, int n_in,
                              void* d_out, int out_size) {
    const float* x   = (const float*)d_in[0];
    const float* c1  = (const float*)d_in[1];
    const float* fw1 = (const float*)d_in[2];
    const float* bw1 = (const float*)d_in[3];
    const float* b1  = (const float*)d_in[4];
    const float* c2  = (const float*)d_in[5];
    const float* fw2 = (const float*)d_in[6];
    const float* bw2 = (const float*)d_in[7];
    const float* b2  = (const float*)d_in[8];
    const float* row = (const float*)d_in[9];
    const float* rob = (const float*)d_in[10];
    float* out = (float*)d_out;
    (void)in_sizes; (void)n_in; (void)out_size;

    // node 1: seed + weight packing + bias-zero flags
    seed_kernel<<<65, 256>>>(x, c1, fw1, bw1, b1, c2, fw2, bw2, b2, row, rob);

    // node 2: one constant-bank upload (D2D, capture-legal)
    void* stage_ptr = nullptr;
    cudaGetSymbolAddress(&stage_ptr, g_stage);
    cudaMemcpyToSymbolAsync(CWc, stage_ptr, sizeof(CW), 0, cudaMemcpyDeviceToDevice);

    // node 3: fused main kernel
    cudaFuncSetAttribute(main_kernel, cudaFuncAttributeMaxDynamicSharedMemorySize,
                         (int)sizeof(Smem));
    dim3 grid(8, 8, BATCH);
    main_kernel<<<grid, 256, sizeof(Smem)>>>(x, out);
}

// round 11
// speedup vs baseline: 1.8265x; 1.0180x over previous
#include <cuda_runtime.h>

#define L 128
#define BATCH 64

typedef unsigned long long u64;

__device__ __forceinline__ float2 cmulf(float2 a, float2 b) {
    return make_float2(a.x*b.x - a.y*b.y, a.x*b.y + a.y*b.x);
}
__device__ __forceinline__ float2 conjf2(float2 a) { return make_float2(a.x, -a.y); }

__device__ __forceinline__ u64 pk2(float a, float b) {
    u64 r; asm("mov.b64 %0, {%1,%2};" : "=l"(r) : "f"(a), "f"(b)); return r;
}
__device__ __forceinline__ void unpk2(u64 v, float& a, float& b) {
    asm("mov.b64 {%0,%1}, %2;" : "=f"(a), "=f"(b) : "l"(v));
}
__device__ __forceinline__ u64 ffma2(u64 a, u64 b, u64 c) {
    u64 d; asm("fma.rn.f32x2 %0, %1, %2, %3;" : "=l"(d) : "l"(a), "l"(b), "l"(c)); return d;
}
__device__ __forceinline__ u64 fmul2(u64 a, u64 b) {
    u64 d; asm("mul.rn.f32x2 %0, %1, %2;" : "=l"(d) : "l"(a), "l"(b)); return d;
}

// ---------------- consolidated weight bank ----------------
struct CW {
    float wD[15][8][2];    // layer1 packed: [tap*3+i][o-pair][2]
    float c2[8][16];       // center2 raw
    float fw2[2][8][16];
    float bw2[2][8][16];
    float b1[16];
    float b2[8];
    float ro[8];
    float rob;
    int   bz1;             // 1 if bias1 is all-zero -> modReLU1 is identity
    int   bz2;             // 1 if bias2 is all-zero -> modReLU2 is identity
    int   pad;
};
__constant__ CW CWc;
__device__ CW g_stage;                 // filled by seed_kernel block 64

// 8 MB scratch for the Wilson-seed (conjugated path), (B, L, L) complex
__device__ float2 g_seed[BATCH * L * L];

// ---------------------------------------------------------------------------
// Kernel 1: Wilson seed (blocks 0..63) + weight packing (block 64)
// ---------------------------------------------------------------------------
__global__ __launch_bounds__(256) void seed_kernel(
    const float* __restrict__ x,
    const float* __restrict__ c1, const float* __restrict__ fw1,
    const float* __restrict__ bw1, const float* __restrict__ b1,
    const float* __restrict__ c2, const float* __restrict__ fw2,
    const float* __restrict__ bw2, const float* __restrict__ b2,
    const float* __restrict__ ro, const float* __restrict__ rob)
{
    int b    = blockIdx.x;
    int tid  = threadIdx.x;

    if (b == 64) {
        if (tid < 120) {
            int k = tid / 8, p = tid % 8;
            int tap = k / 3, i = k % 3;
            const float* W;
            if      (tap == 0) W = c1;
            else if (tap == 1) W = fw1;
            else if (tap == 2) W = fw1 + 48;
            else if (tap == 3) W = bw1;
            else               W = bw1 + 48;
            g_stage.wD[k][p][0] = W[(2*p)*3 + i];
            g_stage.wD[k][p][1] = W[(2*p+1)*3 + i];
        }
        for (int t = tid; t < 128; t += 256) ((float*)g_stage.c2)[t]  = c2[t];
        if (tid < 256) {
            ((float*)g_stage.fw2)[tid] = fw2[tid];
            ((float*)g_stage.bw2)[tid] = bw2[tid];
        }
        if (tid < 16) g_stage.b1[tid] = b1[tid];
        if (tid < 8)  { g_stage.b2[tid] = b2[tid]; g_stage.ro[tid] = ro[tid]; }
        if (tid == 0) {
            g_stage.rob = rob[0];
            int z1 = 1, z2 = 1;
            for (int i = 0; i < 16; i++) if (b1[i] != 0.f) z1 = 0;
            for (int i = 0; i < 8;  i++) if (b2[i] != 0.f) z2 = 0;
            g_stage.bz1 = z1;
            g_stage.bz2 = z2;
        }
        return;
    }

    int w    = tid >> 5;
    int lane = tid & 31;
    __shared__ float2 s_ax[L];
    const float* X = x + (size_t)b * 4 * L * L;

    if (w == 0) {
        float2 u[4];
        #pragma unroll
        for (int t = 0; t < 4; t++) {
            int k = lane * 4 + t;
            u[t] = make_float2(X[0 * L * L + k * L], X[1 * L * L + k * L]);
        }
        float2 e1 = u[0];
        float2 e2 = cmulf(e1, u[1]);
        float2 e3 = cmulf(e2, u[2]);
        float2 v  = cmulf(e3, u[3]);
        #pragma unroll
        for (int off = 1; off < 32; off <<= 1) {
            float vx = __shfl_up_sync(0xffffffffu, v.x, off);
            float vy = __shfl_up_sync(0xffffffffu, v.y, off);
            if (lane >= off) v = cmulf(make_float2(vx, vy), v);
        }
        float wx = __shfl_up_sync(0xffffffffu, v.x, 1);
        float wy = __shfl_up_sync(0xffffffffu, v.y, 1);
        float2 W = (lane == 0) ? make_float2(1.f, 0.f) : make_float2(wx, wy);
        s_ax[lane * 4 + 0] = W;
        s_ax[lane * 4 + 1] = cmulf(W, e1);
        s_ax[lane * 4 + 2] = cmulf(W, e2);
        s_ax[lane * 4 + 3] = cmulf(W, e3);
    }
    __syncthreads();

    float2* seed = g_seed + b * L * L;
    for (int i = w; i < L; i += 8) {
        const float4* pr = reinterpret_cast<const float4*>(X + 2 * L * L + i * L);
        const float4* pi = reinterpret_cast<const float4*>(X + 3 * L * L + i * L);
        float4 r4 = pr[lane], i4 = pi[lane];
        float2 u0 = make_float2(r4.x, i4.x);
        float2 u1 = make_float2(r4.y, i4.y);
        float2 u2 = make_float2(r4.z, i4.z);
        float2 u3 = make_float2(r4.w, i4.w);
        float2 e1 = u0;
        float2 e2 = cmulf(e1, u1);
        float2 e3 = cmulf(e2, u2);
        float2 v  = cmulf(e3, u3);
        #pragma unroll
        for (int off = 1; off < 32; off <<= 1) {
            float vx = __shfl_up_sync(0xffffffffu, v.x, off);
            float vy = __shfl_up_sync(0xffffffffu, v.y, off);
            if (lane >= off) v = cmulf(make_float2(vx, vy), v);
        }
        float wx = __shfl_up_sync(0xffffffffu, v.x, 1);
        float wy = __shfl_up_sync(0xffffffffu, v.y, 1);
        float2 W = (lane == 0) ? make_float2(1.f, 0.f) : make_float2(wx, wy);
        float2 base = cmulf(s_ax[i], W);
        float2 p0 = base;
        float2 p1 = cmulf(base, e1);
        float2 p2 = cmulf(base, e2);
        float2 p3 = cmulf(base, e3);
        float4* dst = reinterpret_cast<float4*>(seed + i * L + lane * 4);
        dst[0] = make_float4(p0.x, -p0.y, p1.x, -p1.y);
        dst[1] = make_float4(p2.x, -p2.y, p3.x, -p3.y);
    }
}

// ---------------------------------------------------------------------------
// Kernel 2: fused main kernel
// ---------------------------------------------------------------------------
struct Smem {
    float2 lx[24][25];        // ux, region [-4, 20)
    float2 ly[24][25];        // uy
    float  pc[22][23];        // cos(plaquette), region [-3, 19)
    float4 f4[20][21];        // {seed.re, seed.im, pavg, pc@(+1,+1)}, region [-2, 18)
    alignas(16) float g1r[18][19][20];   // layer-1 activations SoA [row][col][ch16+pad4]
    alignas(16) float g1i[18][19][20];
};

// layer-2 tap: accumulate  link * (W @ g(neighbor)) with LDS.128 feature loads
__device__ __forceinline__ void tapE(const float* __restrict__ gr,
                                     const float* __restrict__ gi,
                                     const float (&W)[8][16],
                                     float tx, float ty,
                                     u64* ACCr, u64* ACCi) {
    u64 TAr[8], TAi[8];
    #pragma unroll
    for (int o = 0; o < 8; o++) { TAr[o] = 0ull; TAi[o] = 0ull; }
    #pragma unroll
    for (int q = 0; q < 4; q++) {
        longlong2 vr = *reinterpret_cast<const longlong2*>(gr + 4 * q);
        longlong2 vi = *reinterpret_cast<const longlong2*>(gi + 4 * q);
        #pragma unroll
        for (int o = 0; o < 8; o++) {
            u64 wa = *reinterpret_cast<const u64*>(&W[o][4 * q]);
            u64 wb = *reinterpret_cast<const u64*>(&W[o][4 * q + 2]);
            TAr[o] = ffma2(wa, (u64)vr.x, TAr[o]);
            TAr[o] = ffma2(wb, (u64)vr.y, TAr[o]);
            TAi[o] = ffma2(wa, (u64)vi.x, TAi[o]);
            TAi[o] = ffma2(wb, (u64)vi.y, TAi[o]);
        }
    }
    u64 txx = pk2(tx, tx), tyy = pk2(ty, ty), nty = pk2(-ty, -ty);
    #pragma unroll
    for (int o = 0; o < 8; o++) {
        ACCr[o] = ffma2(txx, TAr[o], ffma2(nty, TAi[o], ACCr[o]));
        ACCi[o] = ffma2(txx, TAi[o], ffma2(tyy, TAr[o], ACCi[o]));
    }
}

__global__ __launch_bounds__(256, 3) void main_kernel(
    const float* __restrict__ x, float* __restrict__ out)
{
    extern __shared__ unsigned char smem_raw[];
    Smem& S = *reinterpret_cast<Smem*>(smem_raw);
    int tid = threadIdx.x;
    int b   = blockIdx.z;
    int ti  = blockIdx.y * 16;
    int tj  = blockIdx.x * 16;
    const float* X = x + (size_t)b * 4 * L * L;

    // ---- stage A: link halo (region [-4, 20)), vectorized float4 loads ----
    // 24 rows x 6 col-groups(4 cols) x 2 plane-pairs = 288 tasks.
    // Column groups are 4-aligned mod 128, so no group straddles the wrap.
    for (int t = tid; t < 288; t += 256) {
        int r    = t / 12;
        int rem  = t % 12;
        int grp  = rem >> 1;
        int pair = rem & 1;
        int gi   = (ti + r - 4) & 127;
        int col0 = (tj + grp * 4 - 4) & 127;
        const float* base = X + (2 * pair) * L * L + gi * L + col0;
        float4 re = *reinterpret_cast<const float4*>(base);
        float4 im = *reinterpret_cast<const float4*>(base + L * L);
        float2 (*dst)[25] = pair ? S.ly : S.lx;
        int c = grp * 4;
        dst[r][c + 0] = make_float2(re.x, im.x);
        dst[r][c + 1] = make_float2(re.y, im.y);
        dst[r][c + 2] = make_float2(re.z, im.z);
        dst[r][c + 3] = make_float2(re.w, im.w);
    }
    __syncthreads();

    // ---- stage B: cos(plaquette) (region [-3, 19)) ----
    for (int t = tid; t < 22 * 22; t += 256) {
        int r = t / 22, c = t % 22;
        float2 p = cmulf(S.lx[r + 1][c + 1], S.ly[r + 2][c + 1]);
        p = cmulf(p, conjf2(S.lx[r + 1][c + 2]));
        p = cmulf(p, conjf2(S.ly[r + 1][c + 1]));
        float n = p.x * p.x + p.y * p.y;
        S.pc[r][c] = p.x * rsqrtf(fmaxf(n, 1e-38f));
    }
    __syncthreads();

    // ---- stage C: packed features {sd.re, sd.im, pavg, pc@(+1,+1)} ----
    const float2* seed = g_seed + b * L * L;
    for (int t = tid; t < 20 * 20; t += 256) {
        int r = t / 20, c = t % 20;
        int gi = (ti + r - 2) & 127, gj = (tj + c - 2) & 127;
        float2 sd = seed[gi * L + gj];
        float pcc  = S.pc[r + 1][c + 1];
        float pavg = 0.2f * (pcc + S.pc[r][c + 1] + S.pc[r + 2][c + 1]
                                 + S.pc[r + 1][c] + S.pc[r + 1][c + 2]);
        S.f4[r][c] = make_float4(sd.x, sd.y, pavg, pcc);
    }
    __syncthreads();

    // ---- stage D: lconv1 (factorized) + modReLU (region [-1, 17)) ----
    // out[o] = sum_tap T_tap * (w0[o] + w1[o]*pc_sh + w2[o]*pavg_sh)
    bool bz1 = (CWc.bz1 != 0);
    for (int t = tid; t < 18 * 18; t += 256) {
        int r = t / 18, c = t % 18;    // site f0-idx = (r+1, c+1); x-local = (r+3, c+3)
        float2 l0 = S.lx[r + 3][c + 3], l1 = S.ly[r + 3][c + 3];
        float2 m0 = S.lx[r + 2][c + 3], m1 = S.ly[r + 3][c + 2];

        float4 F0 = S.f4[r + 1][c + 1];   // center
        float4 F1 = S.f4[r + 2][c + 1];   // fwd mu=0
        float4 F2 = S.f4[r + 1][c + 2];   // fwd mu=1
        float4 F3 = S.f4[r    ][c + 1];   // bwd mu=0
        float4 F4 = S.f4[r + 1][c    ];   // bwd mu=1

        float Tr[5], Ti[5], PCv[5], PAv[5];
        Tr[0] = F0.x;                    Ti[0] = F0.y;
        Tr[1] = l0.x * F1.x - l0.y * F1.y; Ti[1] = l0.x * F1.y + l0.y * F1.x;
        Tr[2] = l1.x * F2.x - l1.y * F2.y; Ti[2] = l1.x * F2.y + l1.y * F2.x;
        Tr[3] = m0.x * F3.x + m0.y * F3.y; Ti[3] = m0.x * F3.y - m0.y * F3.x;
        Tr[4] = m1.x * F4.x + m1.y * F4.y; Ti[4] = m1.x * F4.y - m1.y * F4.x;
        PCv[0] = F0.w; PAv[0] = F0.z;
        PCv[1] = F1.w; PAv[1] = F1.z;
        PCv[2] = F2.w; PAv[2] = F2.z;
        PCv[3] = F3.w; PAv[3] = F3.z;
        PCv[4] = F4.w; PAv[4] = F4.z;

        u64 AR[8], AI[8];
        #pragma unroll
        for (int p = 0; p < 8; p++) { AR[p] = 0ull; AI[p] = 0ull; }
        #pragma unroll
        for (int tap = 0; tap < 5; tap++) {
            u64 pc2 = pk2(PCv[tap], PCv[tap]);
            u64 pa2 = pk2(PAv[tap], PAv[tap]);
            u64 trr = pk2(Tr[tap], Tr[tap]);
            u64 tii = pk2(Ti[tap], Ti[tap]);
            #pragma unroll
            for (int p = 0; p < 8; p++) {
                u64 w0 = *reinterpret_cast<const u64*>(&CWc.wD[tap * 3 + 0][p][0]);
                u64 w1 = *reinterpret_cast<const u64*>(&CWc.wD[tap * 3 + 1][p][0]);
                u64 w2 = *reinterpret_cast<const u64*>(&CWc.wD[tap * 3 + 2][p][0]);
                u64 a = ffma2(pa2, w2, ffma2(pc2, w1, w0));
                AR[p] = ffma2(a, trr, AR[p]);
                AI[p] = ffma2(a, tii, AI[p]);
            }
        }
        if (bz1) {
            // bias1 == 0 -> modReLU is exactly identity
            #pragma unroll
            for (int p = 0; p < 8; p++) {
                *reinterpret_cast<u64*>(&S.g1r[r][c][2 * p]) = AR[p];
                *reinterpret_cast<u64*>(&S.g1i[r][c][2 * p]) = AI[p];
            }
        } else {
            #pragma unroll
            for (int p = 0; p < 8; p++) {
                float a0r, a1r, a0i, a1i;
                unpk2(AR[p], a0r, a1r);
                unpk2(AI[p], a0i, a1i);
                float m2a = fmaf(a0r, a0r, fmaf(a0i, a0i, 1e-12f));
                float m2b = fmaf(a1r, a1r, fmaf(a1i, a1i, 1e-12f));
                float q0 = rsqrtf(m2a), q1 = rsqrtf(m2b);
                float s0 = fmaxf(fmaf(CWc.b1[2 * p], q0, 1.f), 0.f);
                float s1 = fmaxf(fmaf(CWc.b1[2 * p + 1], q1, 1.f), 0.f);
                u64 S2 = pk2(s0, s1);
                *reinterpret_cast<u64*>(&S.g1r[r][c][2 * p]) = fmul2(AR[p], S2);
                *reinterpret_cast<u64*>(&S.g1i[r][c][2 * p]) = fmul2(AI[p], S2);
            }
        }
    }
    __syncthreads();

    // ---- stage E: lconv2 + modReLU + readout (16x16 outputs) ----
    {
        int r = tid >> 4, c = tid & 15;   // g1 idx = (r+1, c+1); x-local = (r+4, c+4)
        u64 ACCr[8], ACCi[8];
        #pragma unroll
        for (int o = 0; o < 8; o++) { ACCr[o] = 0ull; ACCi[o] = 0ull; }

        // center tap (no link), LDS.128 loads
        {
            const float* gr = &S.g1r[r + 1][c + 1][0];
            const float* gi = &S.g1i[r + 1][c + 1][0];
            #pragma unroll
            for (int q = 0; q < 4; q++) {
                longlong2 vr = *reinterpret_cast<const longlong2*>(gr + 4 * q);
                longlong2 vi = *reinterpret_cast<const longlong2*>(gi + 4 * q);
                #pragma unroll
                for (int o = 0; o < 8; o++) {
                    u64 wa = *reinterpret_cast<const u64*>(&CWc.c2[o][4 * q]);
                    u64 wb = *reinterpret_cast<const u64*>(&CWc.c2[o][4 * q + 2]);
                    ACCr[o] = ffma2(wa, (u64)vr.x, ACCr[o]);
                    ACCr[o] = ffma2(wb, (u64)vr.y, ACCr[o]);
                    ACCi[o] = ffma2(wa, (u64)vi.x, ACCi[o]);
                    ACCi[o] = ffma2(wb, (u64)vi.y, ACCi[o]);
                }
            }
        }
        float2 l0 = S.lx[r + 4][c + 4], l1 = S.ly[r + 4][c + 4];
        float2 m0 = S.lx[r + 3][c + 4], m1 = S.ly[r + 4][c + 3];
        tapE(&S.g1r[r + 2][c + 1][0], &S.g1i[r + 2][c + 1][0], CWc.fw2[0],  l0.x,  l0.y, ACCr, ACCi);
        tapE(&S.g1r[r + 1][c + 2][0], &S.g1i[r + 1][c + 2][0], CWc.fw2[1],  l1.x,  l1.y, ACCr, ACCi);
        tapE(&S.g1r[r    ][c + 1][0], &S.g1i[r    ][c + 1][0], CWc.bw2[0],  m0.x, -m0.y, ACCr, ACCi);
        tapE(&S.g1r[r + 1][c    ][0], &S.g1i[r + 1][c    ][0], CWc.bw2[1],  m1.x, -m1.y, ACCr, ACCi);

        float val = CWc.rob;
        if (CWc.bz2 != 0) {
            // bias2 == 0 -> scale is exactly 1; inv = m2 directly
            #pragma unroll
            for (int o = 0; o < 8; o++) {
                float rl, rh, il, ih;
                unpk2(ACCr[o], rl, rh);
                unpk2(ACCi[o], il, ih);
                float ar = rl + rh, ai = il + ih;
                float m2 = fmaf(ar, ar, fmaf(ai, ai, 1e-12f));
                val = fmaf(CWc.ro[o], m2, val);
            }
        } else {
            #pragma unroll
            for (int o = 0; o < 8; o++) {
                float rl, rh, il, ih;
                unpk2(ACCr[o], rl, rh);
                unpk2(ACCi[o], il, ih);
                float ar = rl + rh, ai = il + ih;
                float m2 = fmaf(ar, ar, fmaf(ai, ai, 1e-12f));
                float q  = rsqrtf(m2);
                float sc = fmaxf(fmaf(CWc.b2[o], q, 1.f), 0.f);
                val = fmaf(CWc.ro[o], m2 * sc * sc, val);
            }
        }
        out[(size_t)b * L * L + (ti + r) * L + (tj + c)] = val;
    }
}

extern "C" void kernel_launch(void* const* d_in, const int* in_sizes, int n_in,
                              void* d_out, int out_size) {
    const float* x   = (const float*)d_in[0];
    const float* c1  = (const float*)d_in[1];
    const float* fw1 = (const float*)d_in[2];
    const float* bw1 = (const float*)d_in[3];
    const float* b1  = (const float*)d_in[4];
    const float* c2  = (const float*)d_in[5];
    const float* fw2 = (const float*)d_in[6];
    const float* bw2 = (const float*)d_in[7];
    const float* b2  = (const float*)d_in[8];
    const float* row = (const float*)d_in[9];
    const float* rob = (const float*)d_in[10];
    float* out = (float*)d_out;
    (void)in_sizes; (void)n_in; (void)out_size;

    // node 1: seed + weight packing + bias-zero flags
    seed_kernel<<<65, 256>>>(x, c1, fw1, bw1, b1, c2, fw2, bw2, b2, row, rob);

    // node 2: one constant-bank upload (D2D, capture-legal)
    void* stage_ptr = nullptr;
    cudaGetSymbolAddress(&stage_ptr, g_stage);
    cudaMemcpyToSymbolAsync(CWc, stage_ptr, sizeof(CW), 0, cudaMemcpyDeviceToDevice);

    // node 3: fused main kernel
    cudaFuncSetAttribute(main_kernel, cudaFuncAttributeMaxDynamicSharedMemorySize,
                         (int)sizeof(Smem));
    dim3 grid(8, 8, BATCH);
    main_kernel<<<grid, 256, sizeof(Smem)>>>(x, out);
}

// round 12
// speedup vs baseline: 1.9133x; 1.0476x over previous
#include <cuda_runtime.h>

#define L 128
#define BATCH 64

typedef unsigned long long u64;

__device__ __forceinline__ float2 cmulf(float2 a, float2 b) {
    return make_float2(a.x*b.x - a.y*b.y, a.x*b.y + a.y*b.x);
}
__device__ __forceinline__ float2 conjf2(float2 a) { return make_float2(a.x, -a.y); }

__device__ __forceinline__ u64 pk2(float a, float b) {
    u64 r; asm("mov.b64 %0, {%1,%2};" : "=l"(r) : "f"(a), "f"(b)); return r;
}
__device__ __forceinline__ void unpk2(u64 v, float& a, float& b) {
    asm("mov.b64 {%0,%1}, %2;" : "=f"(a), "=f"(b) : "l"(v));
}
__device__ __forceinline__ u64 ffma2(u64 a, u64 b, u64 c) {
    u64 d; asm("fma.rn.f32x2 %0, %1, %2, %3;" : "=l"(d) : "l"(a), "l"(b), "l"(c)); return d;
}
__device__ __forceinline__ u64 fmul2(u64 a, u64 b) {
    u64 d; asm("mul.rn.f32x2 %0, %1, %2;" : "=l"(d) : "l"(a), "l"(b)); return d;
}

// ---------------- consolidated weight bank ----------------
struct CW {
    float wD[15][8][2];    // layer1 packed: [tap*3+i][o-pair][2]
    float c2[8][16];       // center2 raw
    float fw2[2][8][16];
    float bw2[2][8][16];
    float b1[16];
    float b2[8];
    float ro[8];
    float rob;
    int   bz1;             // 1 if bias1 is all-zero -> modReLU1 is identity
    int   bz2;             // 1 if bias2 is all-zero -> modReLU2 is identity
    int   pad;
};
__constant__ CW CWc;
__device__ CW g_stage;                 // filled by seed_kernel block 512

// 8 MB scratch for the Wilson-seed (conjugated path), (B, L, L) complex
__device__ float2 g_seed[BATCH * L * L];

// ---------------------------------------------------------------------------
// Kernel 1: Wilson seed, parallelized over row-groups.
// Blocks 0..511: b = bx>>3, row-group = bx&7 (16 rows, 2 per warp).
// Block 512: weight packing.
// ---------------------------------------------------------------------------
__global__ __launch_bounds__(256) void seed_kernel(
    const float* __restrict__ x,
    const float* __restrict__ c1, const float* __restrict__ fw1,
    const float* __restrict__ bw1, const float* __restrict__ b1,
    const float* __restrict__ c2, const float* __restrict__ fw2,
    const float* __restrict__ bw2, const float* __restrict__ b2,
    const float* __restrict__ ro, const float* __restrict__ rob)
{
    int bx   = blockIdx.x;
    int tid  = threadIdx.x;

    if (bx == 512) {
        if (tid < 120) {
            int k = tid / 8, p = tid % 8;
            int tap = k / 3, i = k % 3;
            const float* W;
            if      (tap == 0) W = c1;
            else if (tap == 1) W = fw1;
            else if (tap == 2) W = fw1 + 48;
            else if (tap == 3) W = bw1;
            else               W = bw1 + 48;
            g_stage.wD[k][p][0] = W[(2*p)*3 + i];
            g_stage.wD[k][p][1] = W[(2*p+1)*3 + i];
        }
        for (int t = tid; t < 128; t += 256) ((float*)g_stage.c2)[t]  = c2[t];
        if (tid < 256) {
            ((float*)g_stage.fw2)[tid] = fw2[tid];
            ((float*)g_stage.bw2)[tid] = bw2[tid];
        }
        if (tid < 16) g_stage.b1[tid] = b1[tid];
        if (tid < 8)  { g_stage.b2[tid] = b2[tid]; g_stage.ro[tid] = ro[tid]; }
        if (tid == 0) {
            g_stage.rob = rob[0];
            int z1 = 1, z2 = 1;
            for (int i = 0; i < 16; i++) if (b1[i] != 0.f) z1 = 0;
            for (int i = 0; i < 8;  i++) if (b2[i] != 0.f) z2 = 0;
            g_stage.bz1 = z1;
            g_stage.bz2 = z2;
        }
        return;
    }

    int b    = bx >> 3;
    int rg   = bx & 7;
    int w    = tid >> 5;
    int lane = tid & 31;
    __shared__ float2 s_ax[L];
    const float* X = x + (size_t)b * 4 * L * L;

    if (w == 0) {
        // exclusive prefix product of ux[:,k,0] over rows k (column 0)
        float2 u[4];
        #pragma unroll
        for (int t = 0; t < 4; t++) {
            int k = lane * 4 + t;
            u[t] = make_float2(X[0 * L * L + k * L], X[1 * L * L + k * L]);
        }
        float2 e1 = u[0];
        float2 e2 = cmulf(e1, u[1]);
        float2 e3 = cmulf(e2, u[2]);
        float2 v  = cmulf(e3, u[3]);
        #pragma unroll
        for (int off = 1; off < 32; off <<= 1) {
            float vx = __shfl_up_sync(0xffffffffu, v.x, off);
            float vy = __shfl_up_sync(0xffffffffu, v.y, off);
            if (lane >= off) v = cmulf(make_float2(vx, vy), v);
        }
        float wx = __shfl_up_sync(0xffffffffu, v.x, 1);
        float wy = __shfl_up_sync(0xffffffffu, v.y, 1);
        float2 W = (lane == 0) ? make_float2(1.f, 0.f) : make_float2(wx, wy);
        s_ax[lane * 4 + 0] = W;
        s_ax[lane * 4 + 1] = cmulf(W, e1);
        s_ax[lane * 4 + 2] = cmulf(W, e2);
        s_ax[lane * 4 + 3] = cmulf(W, e3);
    }
    __syncthreads();

    float2* seed = g_seed + b * L * L;
    #pragma unroll
    for (int k = 0; k < 2; k++) {
        int i = rg * 16 + w * 2 + k;
        const float4* pr = reinterpret_cast<const float4*>(X + 2 * L * L + i * L);
        const float4* pi = reinterpret_cast<const float4*>(X + 3 * L * L + i * L);
        float4 r4 = pr[lane], i4 = pi[lane];
        float2 u0 = make_float2(r4.x, i4.x);
        float2 u1 = make_float2(r4.y, i4.y);
        float2 u2 = make_float2(r4.z, i4.z);
        float2 u3 = make_float2(r4.w, i4.w);
        float2 e1 = u0;
        float2 e2 = cmulf(e1, u1);
        float2 e3 = cmulf(e2, u2);
        float2 v  = cmulf(e3, u3);
        #pragma unroll
        for (int off = 1; off < 32; off <<= 1) {
            float vx = __shfl_up_sync(0xffffffffu, v.x, off);
            float vy = __shfl_up_sync(0xffffffffu, v.y, off);
            if (lane >= off) v = cmulf(make_float2(vx, vy), v);
        }
        float wx = __shfl_up_sync(0xffffffffu, v.x, 1);
        float wy = __shfl_up_sync(0xffffffffu, v.y, 1);
        float2 W = (lane == 0) ? make_float2(1.f, 0.f) : make_float2(wx, wy);
        float2 base = cmulf(s_ax[i], W);
        float2 p0 = base;
        float2 p1 = cmulf(base, e1);
        float2 p2 = cmulf(base, e2);
        float2 p3 = cmulf(base, e3);
        float4* dst = reinterpret_cast<float4*>(seed + i * L + lane * 4);
        dst[0] = make_float4(p0.x, -p0.y, p1.x, -p1.y);
        dst[1] = make_float4(p2.x, -p2.y, p3.x, -p3.y);
    }
}

// ---------------------------------------------------------------------------
// Kernel 2: fused main kernel
// ---------------------------------------------------------------------------
struct Smem {
    float2 lx[24][25];        // ux, region [-4, 20)
    float2 ly[24][25];        // uy
    float  pc[22][23];        // cos(plaquette), region [-3, 19)
    float4 f4[20][21];        // {seed.re, seed.im, pavg, pc@(+1,+1)}, region [-2, 18)
    alignas(16) float g1r[18][19][20];   // layer-1 activations SoA [row][col][ch16+pad4]
    alignas(16) float g1i[18][19][20];
};

// layer-2 tap: accumulate  link * (W @ g(neighbor)) with LDS.128 feature loads
__device__ __forceinline__ void tapE(const float* __restrict__ gr,
                                     const float* __restrict__ gi,
                                     const float (&W)[8][16],
                                     float tx, float ty,
                                     u64* ACCr, u64* ACCi) {
    u64 TAr[8], TAi[8];
    #pragma unroll
    for (int o = 0; o < 8; o++) { TAr[o] = 0ull; TAi[o] = 0ull; }
    #pragma unroll
    for (int q = 0; q < 4; q++) {
        longlong2 vr = *reinterpret_cast<const longlong2*>(gr + 4 * q);
        longlong2 vi = *reinterpret_cast<const longlong2*>(gi + 4 * q);
        #pragma unroll
        for (int o = 0; o < 8; o++) {
            u64 wa = *reinterpret_cast<const u64*>(&W[o][4 * q]);
            u64 wb = *reinterpret_cast<const u64*>(&W[o][4 * q + 2]);
            TAr[o] = ffma2(wa, (u64)vr.x, TAr[o]);
            TAr[o] = ffma2(wb, (u64)vr.y, TAr[o]);
            TAi[o] = ffma2(wa, (u64)vi.x, TAi[o]);
            TAi[o] = ffma2(wb, (u64)vi.y, TAi[o]);
        }
    }
    u64 txx = pk2(tx, tx), tyy = pk2(ty, ty), nty = pk2(-ty, -ty);
    #pragma unroll
    for (int o = 0; o < 8; o++) {
        ACCr[o] = ffma2(txx, TAr[o], ffma2(nty, TAi[o], ACCr[o]));
        ACCi[o] = ffma2(txx, TAi[o], ffma2(tyy, TAr[o], ACCi[o]));
    }
}

__global__ __launch_bounds__(256, 3) void main_kernel(
    const float* __restrict__ x, float* __restrict__ out)
{
    extern __shared__ unsigned char smem_raw[];
    Smem& S = *reinterpret_cast<Smem*>(smem_raw);
    int tid = threadIdx.x;
    int b   = blockIdx.z;
    int ti  = blockIdx.y * 16;
    int tj  = blockIdx.x * 16;
    const float* X = x + (size_t)b * 4 * L * L;

    // ---- stage A: link halo (region [-4, 20)), vectorized float4 loads ----
    for (int t = tid; t < 288; t += 256) {
        int r    = t / 12;
        int rem  = t % 12;
        int grp  = rem >> 1;
        int pair = rem & 1;
        int gi   = (ti + r - 4) & 127;
        int col0 = (tj + grp * 4 - 4) & 127;
        const float* base = X + (2 * pair) * L * L + gi * L + col0;
        float4 re = *reinterpret_cast<const float4*>(base);
        float4 im = *reinterpret_cast<const float4*>(base + L * L);
        float2 (*dst)[25] = pair ? S.ly : S.lx;
        int c = grp * 4;
        dst[r][c + 0] = make_float2(re.x, im.x);
        dst[r][c + 1] = make_float2(re.y, im.y);
        dst[r][c + 2] = make_float2(re.z, im.z);
        dst[r][c + 3] = make_float2(re.w, im.w);
    }
    __syncthreads();

    // ---- stage B: cos(plaquette) (region [-3, 19)) ----
    for (int t = tid; t < 22 * 22; t += 256) {
        int r = t / 22, c = t % 22;
        float2 p = cmulf(S.lx[r + 1][c + 1], S.ly[r + 2][c + 1]);
        p = cmulf(p, conjf2(S.lx[r + 1][c + 2]));
        p = cmulf(p, conjf2(S.ly[r + 1][c + 1]));
        float n = p.x * p.x + p.y * p.y;
        S.pc[r][c] = p.x * rsqrtf(fmaxf(n, 1e-38f));
    }
    __syncthreads();

    // ---- stage C: packed features, vectorized seed loads (single pass) ----
    // Each task loads one float4 = 2 complex seed sites (even global col),
    // covering f4 cols 2q-2, 2q-1 for q in [1,10].
    const float2* seed = g_seed + b * L * L;
    {
        int t = tid;
        if (t < 200) {
            int r = t / 10, q = t % 10 + 1;
            int gi = (ti + r - 2) & 127;
            int gj = (tj - 4 + 2 * q) & 127;          // even, no wrap inside pair
            float4 sd2 = *reinterpret_cast<const float4*>(seed + gi * L + gj);
            int c0 = 2 * q - 2;
            #pragma unroll
            for (int k = 0; k < 2; k++) {
                int c = c0 + k;
                float sx = k ? sd2.z : sd2.x;
                float sy = k ? sd2.w : sd2.y;
                float pcc  = S.pc[r + 1][c + 1];
                float pavg = 0.2f * (pcc + S.pc[r][c + 1] + S.pc[r + 2][c + 1]
                                         + S.pc[r + 1][c] + S.pc[r + 1][c + 2]);
                S.f4[r][c] = make_float4(sx, sy, pavg, pcc);
            }
        }
    }
    __syncthreads();

    // ---- stage D: lconv1 (factorized) + modReLU (region [-1, 17)) ----
    bool bz1 = (CWc.bz1 != 0);
    for (int t = tid; t < 18 * 18; t += 256) {
        int r = t / 18, c = t % 18;    // site f0-idx = (r+1, c+1); x-local = (r+3, c+3)
        float2 l0 = S.lx[r + 3][c + 3], l1 = S.ly[r + 3][c + 3];
        float2 m0 = S.lx[r + 2][c + 3], m1 = S.ly[r + 3][c + 2];

        float4 F0 = S.f4[r + 1][c + 1];   // center
        float4 F1 = S.f4[r + 2][c + 1];   // fwd mu=0
        float4 F2 = S.f4[r + 1][c + 2];   // fwd mu=1
        float4 F3 = S.f4[r    ][c + 1];   // bwd mu=0
        float4 F4 = S.f4[r + 1][c    ];   // bwd mu=1

        float Tr[5], Ti[5], PCv[5], PAv[5];
        Tr[0] = F0.x;                    Ti[0] = F0.y;
        Tr[1] = l0.x * F1.x - l0.y * F1.y; Ti[1] = l0.x * F1.y + l0.y * F1.x;
        Tr[2] = l1.x * F2.x - l1.y * F2.y; Ti[2] = l1.x * F2.y + l1.y * F2.x;
        Tr[3] = m0.x * F3.x + m0.y * F3.y; Ti[3] = m0.x * F3.y - m0.y * F3.x;
        Tr[4] = m1.x * F4.x + m1.y * F4.y; Ti[4] = m1.x * F4.y - m1.y * F4.x;
        PCv[0] = F0.w; PAv[0] = F0.z;
        PCv[1] = F1.w; PAv[1] = F1.z;
        PCv[2] = F2.w; PAv[2] = F2.z;
        PCv[3] = F3.w; PAv[3] = F3.z;
        PCv[4] = F4.w; PAv[4] = F4.z;

        u64 AR[8], AI[8];
        #pragma unroll
        for (int p = 0; p < 8; p++) { AR[p] = 0ull; AI[p] = 0ull; }
        #pragma unroll
        for (int tap = 0; tap < 5; tap++) {
            u64 pc2 = pk2(PCv[tap], PCv[tap]);
            u64 pa2 = pk2(PAv[tap], PAv[tap]);
            u64 trr = pk2(Tr[tap], Tr[tap]);
            u64 tii = pk2(Ti[tap], Ti[tap]);
            #pragma unroll
            for (int p = 0; p < 8; p++) {
                u64 w0 = *reinterpret_cast<const u64*>(&CWc.wD[tap * 3 + 0][p][0]);
                u64 w1 = *reinterpret_cast<const u64*>(&CWc.wD[tap * 3 + 1][p][0]);
                u64 w2 = *reinterpret_cast<const u64*>(&CWc.wD[tap * 3 + 2][p][0]);
                u64 a = ffma2(pa2, w2, ffma2(pc2, w1, w0));
                AR[p] = ffma2(a, trr, AR[p]);
                AI[p] = ffma2(a, tii, AI[p]);
            }
        }
        if (bz1) {
            #pragma unroll
            for (int p = 0; p < 8; p++) {
                *reinterpret_cast<u64*>(&S.g1r[r][c][2 * p]) = AR[p];
                *reinterpret_cast<u64*>(&S.g1i[r][c][2 * p]) = AI[p];
            }
        } else {
            #pragma unroll
            for (int p = 0; p < 8; p++) {
                float a0r, a1r, a0i, a1i;
                unpk2(AR[p], a0r, a1r);
                unpk2(AI[p], a0i, a1i);
                float m2a = fmaf(a0r, a0r, fmaf(a0i, a0i, 1e-12f));
                float m2b = fmaf(a1r, a1r, fmaf(a1i, a1i, 1e-12f));
                float q0 = rsqrtf(m2a), q1 = rsqrtf(m2b);
                float s0 = fmaxf(fmaf(CWc.b1[2 * p], q0, 1.f), 0.f);
                float s1 = fmaxf(fmaf(CWc.b1[2 * p + 1], q1, 1.f), 0.f);
                u64 S2 = pk2(s0, s1);
                *reinterpret_cast<u64*>(&S.g1r[r][c][2 * p]) = fmul2(AR[p], S2);
                *reinterpret_cast<u64*>(&S.g1i[r][c][2 * p]) = fmul2(AI[p], S2);
            }
        }
    }
    __syncthreads();

    // ---- stage E: lconv2 + modReLU + readout (16x16 outputs) ----
    {
        int r = tid >> 4, c = tid & 15;   // g1 idx = (r+1, c+1); x-local = (r+4, c+4)
        // hoist link loads so their latency overlaps the center matvec
        float2 l0 = S.lx[r + 4][c + 4], l1 = S.ly[r + 4][c + 4];
        float2 m0 = S.lx[r + 3][c + 4], m1 = S.ly[r + 4][c + 3];

        u64 ACCr[8], ACCi[8];
        #pragma unroll
        for (int o = 0; o < 8; o++) { ACCr[o] = 0ull; ACCi[o] = 0ull; }

        // center tap (no link), LDS.128 loads
        {
            const float* gr = &S.g1r[r + 1][c + 1][0];
            const float* gi = &S.g1i[r + 1][c + 1][0];
            #pragma unroll
            for (int q = 0; q < 4; q++) {
                longlong2 vr = *reinterpret_cast<const longlong2*>(gr + 4 * q);
                longlong2 vi = *reinterpret_cast<const longlong2*>(gi + 4 * q);
                #pragma unroll
                for (int o = 0; o < 8; o++) {
                    u64 wa = *reinterpret_cast<const u64*>(&CWc.c2[o][4 * q]);
                    u64 wb = *reinterpret_cast<const u64*>(&CWc.c2[o][4 * q + 2]);
                    ACCr[o] = ffma2(wa, (u64)vr.x, ACCr[o]);
                    ACCr[o] = ffma2(wb, (u64)vr.y, ACCr[o]);
                    ACCi[o] = ffma2(wa, (u64)vi.x, ACCi[o]);
                    ACCi[o] = ffma2(wb, (u64)vi.y, ACCi[o]);
                }
            }
        }
        tapE(&S.g1r[r + 2][c + 1][0], &S.g1i[r + 2][c + 1][0], CWc.fw2[0],  l0.x,  l0.y, ACCr, ACCi);
        tapE(&S.g1r[r + 1][c + 2][0], &S.g1i[r + 1][c + 2][0], CWc.fw2[1],  l1.x,  l1.y, ACCr, ACCi);
        tapE(&S.g1r[r    ][c + 1][0], &S.g1i[r    ][c + 1][0], CWc.bw2[0],  m0.x, -m0.y, ACCr, ACCi);
        tapE(&S.g1r[r + 1][c    ][0], &S.g1i[r + 1][c    ][0], CWc.bw2[1],  m1.x, -m1.y, ACCr, ACCi);

        float val = CWc.rob;
        if (CWc.bz2 != 0) {
            #pragma unroll
            for (int o = 0; o < 8; o++) {
                float rl, rh, il, ih;
                unpk2(ACCr[o], rl, rh);
                unpk2(ACCi[o], il, ih);
                float ar = rl + rh, ai = il + ih;
                float m2 = fmaf(ar, ar, fmaf(ai, ai, 1e-12f));
                val = fmaf(CWc.ro[o], m2, val);
            }
        } else {
            #pragma unroll
            for (int o = 0; o < 8; o++) {
                float rl, rh, il, ih;
                unpk2(ACCr[o], rl, rh);
                unpk2(ACCi[o], il, ih);
                float ar = rl + rh, ai = il + ih;
                float m2 = fmaf(ar, ar, fmaf(ai, ai, 1e-12f));
                float q  = rsqrtf(m2);
                float sc = fmaxf(fmaf(CWc.b2[o], q, 1.f), 0.f);
                val = fmaf(CWc.ro[o], m2 * sc * sc, val);
            }
        }
        out[(size_t)b * L * L + (ti + r) * L + (tj + c)] = val;
    }
}

extern "C" void kernel_launch(void* const* d_in, const int* in_sizes, int n_in,
                              void* d_out, int out_size) {
    const float* x   = (const float*)d_in[0];
    const float* c1  = (const float*)d_in[1];
    const float* fw1 = (const float*)d_in[2];
    const float* bw1 = (const float*)d_in[3];
    const float* b1  = (const float*)d_in[4];
    const float* c2  = (const float*)d_in[5];
    const float* fw2 = (const float*)d_in[6];
    const float* bw2 = (const float*)d_in[7];
    const float* b2  = (const float*)d_in[8];
    const float* row = (const float*)d_in[9];
    const float* rob = (const float*)d_in[10];
    float* out = (float*)d_out;
    (void)in_sizes; (void)n_in; (void)out_size;

    // node 1: seed (parallel rows) + weight packing + bias-zero flags
    seed_kernel<<<513, 256>>>(x, c1, fw1, bw1, b1, c2, fw2, bw2, b2, row, rob);

    // node 2: one constant-bank upload (D2D, capture-legal)
    void* stage_ptr = nullptr;
    cudaGetSymbolAddress(&stage_ptr, g_stage);
    cudaMemcpyToSymbolAsync(CWc, stage_ptr, sizeof(CW), 0, cudaMemcpyDeviceToDevice);

    // node 3: fused main kernel
    cudaFuncSetAttribute(main_kernel, cudaFuncAttributeMaxDynamicSharedMemorySize,
                         (int)sizeof(Smem));
    dim3 grid(8, 8, BATCH);
    main_kernel<<<grid, 256, sizeof(Smem)>>>(x, out);
}